// round 1
// baseline (speedup 1.0000x reference)
#include <cuda_runtime.h>

// Problem constants
#define BB 4
#define CC 256
#define NN 4096

// Scratch (allocation-free rule: __device__ globals)
__device__ float g_q[BB * CC * NN];                 // 16 MB
__device__ float g_k[BB * CC * NN];                 // 16 MB
__device__ float g_v[BB * CC * NN];                 // 16 MB
__device__ float g_e[(size_t)BB * NN * NN];         // 256 MB (energy -> attn in-place)

// ---------------------------------------------------------------------------
// Tiling config shared by all GEMM kernels:
//   block tile 128x128, BK=16, 256 threads, 8x8 per-thread micro-tile.
//   smem padded to 132 floats/row: keeps float4 alignment (528B % 16 == 0)
//   and reduces transpose-scatter bank conflicts to 2-way.
// ---------------------------------------------------------------------------
#define BK 16
#define SMP 132

__device__ __forceinline__ void mma_tile(const float (*sA)[SMP], const float (*sB)[SMP],
                                         float acc[8][8], int tr, int tc) {
#pragma unroll
    for (int k = 0; k < BK; ++k) {
        float a[8], b[8];
        *(float4*)&a[0] = *(const float4*)&sA[k][tr];
        *(float4*)&a[4] = *(const float4*)&sA[k][tr + 4];
        *(float4*)&b[0] = *(const float4*)&sB[k][tc];
        *(float4*)&b[4] = *(const float4*)&sB[k][tc + 4];
#pragma unroll
        for (int i = 0; i < 8; ++i)
#pragma unroll
            for (int j = 0; j < 8; ++j)
                acc[i][j] = fmaf(a[i], b[j], acc[i][j]);
    }
}

// ---------------------------------------------------------------------------
// Kernel 1: fused QKV.  out[b,d,n] = sum_c W[d,c] * X[b,c,n] + bias[d]
// blockIdx.z encodes (batch, proj). A = W (row-major MxK, transposed load),
// B = X ([C,N], direct load).
// ---------------------------------------------------------------------------
__global__ __launch_bounds__(256) void qkv_kernel(
    const float* __restrict__ x,
    const float* __restrict__ wq, const float* __restrict__ bq,
    const float* __restrict__ wk, const float* __restrict__ bk,
    const float* __restrict__ wv, const float* __restrict__ bv)
{
    const int z = blockIdx.z;
    const int b = z / 3, proj = z % 3;
    const float* W    = (proj == 0) ? wq : (proj == 1) ? wk : wv;
    const float* bias = (proj == 0) ? bq : (proj == 1) ? bk : bv;
    float* out = ((proj == 0) ? g_q : (proj == 1) ? g_k : g_v) + (size_t)b * CC * NN;
    const float* X = x + (size_t)b * CC * NN;

    const int m0 = blockIdx.y * 128;
    const int n0 = blockIdx.x * 128;
    const int tid = threadIdx.x;

    __shared__ float sA[BK][SMP];
    __shared__ float sB[BK][SMP];
    float acc[8][8] = {};

    for (int k0 = 0; k0 < CC; k0 += BK) {
        // A: W[(m0+r)*C + k0+kg..+3] -> sA[kg..kg+3][r]   (transpose)
#pragma unroll
        for (int t = 0; t < 2; ++t) {
            int idx = tid + t * 256;
            int r = idx >> 2, kg = (idx & 3) << 2;
            float4 a4 = *(const float4*)(W + (size_t)(m0 + r) * CC + k0 + kg);
            sA[kg + 0][r] = a4.x; sA[kg + 1][r] = a4.y;
            sA[kg + 2][r] = a4.z; sA[kg + 3][r] = a4.w;
        }
        // B: X[(k0+r)*N + n0 + c] -> sB[r][c]   (direct)
#pragma unroll
        for (int t = 0; t < 2; ++t) {
            int idx = tid + t * 256;
            int r = idx >> 5, c4 = idx & 31;
            float4 b4 = *(const float4*)(X + (size_t)(k0 + r) * NN + n0 + c4 * 4);
            *(float4*)&sB[r][c4 * 4] = b4;
        }
        __syncthreads();
        mma_tile(sA, sB, acc, (tid >> 4) << 3, (tid & 15) << 3);
        __syncthreads();
    }

    const int tr = (tid >> 4) << 3;
    const int tc = (tid & 15) << 3;
#pragma unroll
    for (int i = 0; i < 8; ++i) {
        float bi = bias[m0 + tr + i];
        float4 o0, o1;
        o0.x = acc[i][0] + bi; o0.y = acc[i][1] + bi; o0.z = acc[i][2] + bi; o0.w = acc[i][3] + bi;
        o1.x = acc[i][4] + bi; o1.y = acc[i][5] + bi; o1.z = acc[i][6] + bi; o1.w = acc[i][7] + bi;
        float* op = out + (size_t)(m0 + tr + i) * NN + n0 + tc;
        *(float4*)(op)     = o0;
        *(float4*)(op + 4) = o1;
    }
}

// ---------------------------------------------------------------------------
// Kernel 2: energy.  E[b,i,j] = sum_c Q[b,c,i] * K[b,c,j]
// Both operands K-major-outer ([C,N], i/j contiguous) -> both direct loads.
// ---------------------------------------------------------------------------
__global__ __launch_bounds__(256) void energy_kernel()
{
    const int b = blockIdx.z;
    const float* Q = g_q + (size_t)b * CC * NN;
    const float* K = g_k + (size_t)b * CC * NN;
    float* E = g_e + (size_t)b * NN * NN;

    const int m0 = blockIdx.y * 128;   // i
    const int n0 = blockIdx.x * 128;   // j
    const int tid = threadIdx.x;

    __shared__ float sA[BK][SMP];
    __shared__ float sB[BK][SMP];
    float acc[8][8] = {};

    for (int k0 = 0; k0 < CC; k0 += BK) {
#pragma unroll
        for (int t = 0; t < 2; ++t) {
            int idx = tid + t * 256;
            int r = idx >> 5, c4 = idx & 31;
            float4 a4 = *(const float4*)(Q + (size_t)(k0 + r) * NN + m0 + c4 * 4);
            *(float4*)&sA[r][c4 * 4] = a4;
            float4 b4 = *(const float4*)(K + (size_t)(k0 + r) * NN + n0 + c4 * 4);
            *(float4*)&sB[r][c4 * 4] = b4;
        }
        __syncthreads();
        mma_tile(sA, sB, acc, (tid >> 4) << 3, (tid & 15) << 3);
        __syncthreads();
    }

    const int tr = (tid >> 4) << 3;
    const int tc = (tid & 15) << 3;
#pragma unroll
    for (int i = 0; i < 8; ++i) {
        float* ep = E + (size_t)(m0 + tr + i) * NN + n0 + tc;
        *(float4*)(ep)     = make_float4(acc[i][0], acc[i][1], acc[i][2], acc[i][3]);
        *(float4*)(ep + 4) = make_float4(acc[i][4], acc[i][5], acc[i][6], acc[i][7]);
    }
}

// ---------------------------------------------------------------------------
// Kernel 3: in-place row softmax over j. One block per row (B*N rows).
// ---------------------------------------------------------------------------
__global__ __launch_bounds__(256) void softmax_kernel()
{
    const size_t row = blockIdx.x;
    float* p = g_e + row * (size_t)NN;
    const int tid = threadIdx.x;

    float4 v[4];
    float mx = -1e30f;
#pragma unroll
    for (int t = 0; t < 4; ++t) {
        v[t] = ((const float4*)p)[tid + t * 256];
        mx = fmaxf(mx, fmaxf(fmaxf(v[t].x, v[t].y), fmaxf(v[t].z, v[t].w)));
    }

    __shared__ float red[8];
#pragma unroll
    for (int o = 16; o > 0; o >>= 1) mx = fmaxf(mx, __shfl_xor_sync(0xffffffffu, mx, o));
    if ((tid & 31) == 0) red[tid >> 5] = mx;
    __syncthreads();
    mx = red[0];
#pragma unroll
    for (int w = 1; w < 8; ++w) mx = fmaxf(mx, red[w]);
    __syncthreads();

    float sum = 0.f;
#pragma unroll
    for (int t = 0; t < 4; ++t) {
        v[t].x = __expf(v[t].x - mx); v[t].y = __expf(v[t].y - mx);
        v[t].z = __expf(v[t].z - mx); v[t].w = __expf(v[t].w - mx);
        sum += v[t].x + v[t].y + v[t].z + v[t].w;
    }
#pragma unroll
    for (int o = 16; o > 0; o >>= 1) sum += __shfl_xor_sync(0xffffffffu, sum, o);
    if ((tid & 31) == 0) red[tid >> 5] = sum;
    __syncthreads();
    sum = 0.f;
#pragma unroll
    for (int w = 0; w < 8; ++w) sum += red[w];

    const float inv = 1.0f / sum;
#pragma unroll
    for (int t = 0; t < 4; ++t) {
        v[t].x *= inv; v[t].y *= inv; v[t].z *= inv; v[t].w *= inv;
        ((float4*)p)[tid + t * 256] = v[t];
    }
}

// ---------------------------------------------------------------------------
// Kernel 4: va + residual.  out[b,c,i] = pose[b,c,i] + gamma * sum_j V[b,c,j]*P[b,i,j]
// A = V ([C,N], row-major MxK -> transpose load), B = P ([N,N], row-major NxK
// -> transpose load). K loop over j (4096).
// ---------------------------------------------------------------------------
__global__ __launch_bounds__(256) void va_kernel(
    const float* __restrict__ pose,
    const float* __restrict__ gamma,
    float* __restrict__ out)
{
    const int b = blockIdx.z;
    const float* V = g_v + (size_t)b * CC * NN;
    const float* P = g_e + (size_t)b * NN * NN;

    const int m0 = blockIdx.y * 128;   // c
    const int n0 = blockIdx.x * 128;   // i
    const int tid = threadIdx.x;

    __shared__ float sA[BK][SMP];
    __shared__ float sB[BK][SMP];
    float acc[8][8] = {};

    for (int k0 = 0; k0 < NN; k0 += BK) {
#pragma unroll
        for (int t = 0; t < 2; ++t) {
            int idx = tid + t * 256;
            int r = idx >> 2, kg = (idx & 3) << 2;
            float4 a4 = *(const float4*)(V + (size_t)(m0 + r) * NN + k0 + kg);
            sA[kg + 0][r] = a4.x; sA[kg + 1][r] = a4.y;
            sA[kg + 2][r] = a4.z; sA[kg + 3][r] = a4.w;
            float4 b4 = *(const float4*)(P + (size_t)(n0 + r) * NN + k0 + kg);
            sB[kg + 0][r] = b4.x; sB[kg + 1][r] = b4.y;
            sB[kg + 2][r] = b4.z; sB[kg + 3][r] = b4.w;
        }
        __syncthreads();
        mma_tile(sA, sB, acc, (tid >> 4) << 3, (tid & 15) << 3);
        __syncthreads();
    }

    const float g = gamma[0];
    const int tr = (tid >> 4) << 3;
    const int tc = (tid & 15) << 3;
#pragma unroll
    for (int i = 0; i < 8; ++i) {
        const size_t base = ((size_t)b * CC + (m0 + tr + i)) * NN + n0 + tc;
        float4 p0 = *(const float4*)(pose + base);
        float4 p1 = *(const float4*)(pose + base + 4);
        float4 o0, o1;
        o0.x = fmaf(g, acc[i][0], p0.x); o0.y = fmaf(g, acc[i][1], p0.y);
        o0.z = fmaf(g, acc[i][2], p0.z); o0.w = fmaf(g, acc[i][3], p0.w);
        o1.x = fmaf(g, acc[i][4], p1.x); o1.y = fmaf(g, acc[i][5], p1.y);
        o1.z = fmaf(g, acc[i][6], p1.z); o1.w = fmaf(g, acc[i][7], p1.w);
        *(float4*)(out + base)     = o0;
        *(float4*)(out + base + 4) = o1;
    }
}

// ---------------------------------------------------------------------------
extern "C" void kernel_launch(void* const* d_in, const int* in_sizes, int n_in,
                              void* d_out, int out_size)
{
    const float* pose  = (const float*)d_in[0];
    const float* wq    = (const float*)d_in[1];
    const float* bq    = (const float*)d_in[2];
    const float* wk    = (const float*)d_in[3];
    const float* bk    = (const float*)d_in[4];
    const float* wv    = (const float*)d_in[5];
    const float* bv    = (const float*)d_in[6];
    const float* gamma = (const float*)d_in[7];
    float* out = (float*)d_out;

    dim3 blk(256);
    qkv_kernel   <<<dim3(NN / 128, CC / 128, 3 * BB), blk>>>(pose, wq, bq, wk, bk, wv, bv);
    energy_kernel<<<dim3(NN / 128, NN / 128, BB),     blk>>>();
    softmax_kernel<<<dim3(BB * NN),                   blk>>>();
    va_kernel    <<<dim3(NN / 128, CC / 128, BB),     blk>>>(pose, gamma, out);
}

// round 5
// speedup vs baseline: 2.3936x; 2.3936x over previous
#include <cuda_runtime.h>
#include <cuda_bf16.h>
#include <cstdint>

#define BB 4
#define CC 256
#define NN 4096

// Scratch (__device__ globals — allocation-free rule)
__device__ float g_qt[BB * NN * CC];                 // Qt [B,N,C]
__device__ float g_kt[BB * NN * CC];                 // Kt [B,N,C]
__device__ float g_v [(size_t)BB * CC * NN];         // V  [B,C,N]
__device__ float g_xt[BB * NN * CC];                 // Xt [B,N,C]
__device__ float g_e [(size_t)BB * NN * NN];         // E / P [B,N,N]

#define SMP 40        // padded smem row: 40 bf16 = 80B -> ldmatrix conflict-free

static __device__ __forceinline__ uint32_t smem_u32(const void* p) {
    uint32_t a;
    asm("{ .reg .u64 t; cvta.to.shared.u64 t, %1; cvt.u32.u64 %0, t; }" : "=r"(a) : "l"(p));
    return a;
}
static __device__ __forceinline__ void ldmx4(uint32_t& r0, uint32_t& r1, uint32_t& r2,
                                             uint32_t& r3, uint32_t addr) {
    asm volatile("ldmatrix.sync.aligned.m8n8.x4.shared.b16 {%0,%1,%2,%3}, [%4];"
                 : "=r"(r0), "=r"(r1), "=r"(r2), "=r"(r3) : "r"(addr));
}
static __device__ __forceinline__ void ldmx2(uint32_t& r0, uint32_t& r1, uint32_t addr) {
    asm volatile("ldmatrix.sync.aligned.m8n8.x2.shared.b16 {%0,%1}, [%2];"
                 : "=r"(r0), "=r"(r1) : "r"(addr));
}
static __device__ __forceinline__ void mma16816(float* d, uint32_t a0, uint32_t a1,
                                                uint32_t a2, uint32_t a3,
                                                uint32_t b0, uint32_t b1) {
    asm volatile(
        "mma.sync.aligned.m16n8k16.row.col.f32.bf16.bf16.f32 "
        "{%0,%1,%2,%3}, {%4,%5,%6,%7}, {%8,%9}, {%0,%1,%2,%3};"
        : "+f"(d[0]), "+f"(d[1]), "+f"(d[2]), "+f"(d[3])
        : "r"(a0), "r"(a1), "r"(a2), "r"(a3), "r"(b0), "r"(b1));
}

// Convert float4 -> hi/lo bf16x2 pairs and store 8B each to padded smem.
static __device__ __forceinline__ void cv_store(
    __nv_bfloat16* hi, __nv_bfloat16* lo, int off, float4 x)
{
    __nv_bfloat162 h0 = __floats2bfloat162_rn(x.x, x.y);
    __nv_bfloat162 h1 = __floats2bfloat162_rn(x.z, x.w);
    float2 f0 = __bfloat1622float2(h0);
    float2 f1 = __bfloat1622float2(h1);
    __nv_bfloat162 l0 = __floats2bfloat162_rn(x.x - f0.x, x.y - f0.y);
    __nv_bfloat162 l1 = __floats2bfloat162_rn(x.z - f1.x, x.w - f1.y);
    uint2 vh, vl;
    vh.x = *(uint32_t*)&h0; vh.y = *(uint32_t*)&h1;
    vl.x = *(uint32_t*)&l0; vl.y = *(uint32_t*)&l1;
    *(uint2*)(hi + off) = vh;
    *(uint2*)(lo + off) = vl;
}

// ---------------------------------------------------------------------------
// Core: acc[4][4][4] += A[128,K] * B[128,K]^T  (block tile 128x128, BK=32,
// 256 threads, warp grid 2(m) x 4(n), warp tile 64x32, split-bf16 3-term).
// ---------------------------------------------------------------------------
static __device__ __forceinline__ void gemm_core(
    const float* __restrict__ A, int lda,
    const float* __restrict__ B, int ldb,
    int kiters,
    __nv_bfloat16* sAhi, __nv_bfloat16* sAlo,
    __nv_bfloat16* sBhi, __nv_bfloat16* sBlo,
    float acc[4][4][4])
{
    const int tid = threadIdx.x;
    const int lane = tid & 31;
    const int wid = tid >> 5;
    const int wm = wid & 1;          // 0..1 -> m offset 0/64
    const int wn = wid >> 1;         // 0..3 -> n offset 0/32/64/96

    const uint32_t sAhi_u = smem_u32(sAhi);
    const uint32_t sAlo_u = smem_u32(sAlo);
    const uint32_t sBhi_u = smem_u32(sBhi);
    const uint32_t sBlo_u = smem_u32(sBlo);

    // ldmatrix lane addressing (bytes)
    const uint32_t a_off = ((wm * 64 + (lane & 15)) * SMP + (lane >> 4) * 8) * 2;
    const uint32_t b_off = ((wn * 32 + (lane & 7)) * SMP + ((lane >> 3) & 1) * 8) * 2;

    const int ldrow = tid >> 3;            // 32 rows per pass, 4 passes = 128
    const int ldcol = (tid & 7) << 2;      // 0,4,..,28

    for (int kb = 0; kb < kiters; ++kb) {
        const int k0 = kb * 32;
#pragma unroll
        for (int it = 0; it < 4; ++it) {
            const int row = ldrow + it * 32;
            float4 xa = *(const float4*)(A + (size_t)row * lda + k0 + ldcol);
            cv_store(sAhi, sAlo, row * SMP + ldcol, xa);
            float4 xb = *(const float4*)(B + (size_t)row * ldb + k0 + ldcol);
            cv_store(sBhi, sBlo, row * SMP + ldcol, xb);
        }
        __syncthreads();

#pragma unroll
        for (int ks = 0; ks < 2; ++ks) {
            const uint32_t kofs = ks * 16 * 2;
            uint32_t bh[4][2], bl[4][2];
#pragma unroll
            for (int nt = 0; nt < 4; ++nt) {
                const uint32_t bo = b_off + kofs + nt * (8 * SMP * 2);
                ldmx2(bh[nt][0], bh[nt][1], sBhi_u + bo);
                ldmx2(bl[nt][0], bl[nt][1], sBlo_u + bo);
            }
#pragma unroll
            for (int mt = 0; mt < 4; ++mt) {
                const uint32_t ao = a_off + kofs + mt * (16 * SMP * 2);
                uint32_t ah0, ah1, ah2, ah3, al0, al1, al2, al3;
                ldmx4(ah0, ah1, ah2, ah3, sAhi_u + ao);
                ldmx4(al0, al1, al2, al3, sAlo_u + ao);
#pragma unroll
                for (int nt = 0; nt < 4; ++nt) {
                    mma16816(acc[mt][nt], ah0, ah1, ah2, ah3, bh[nt][0], bh[nt][1]);
                    mma16816(acc[mt][nt], ah0, ah1, ah2, ah3, bl[nt][0], bl[nt][1]);
                    mma16816(acc[mt][nt], al0, al1, al2, al3, bh[nt][0], bh[nt][1]);
                }
            }
        }
        __syncthreads();
    }
}

// Fragment->matrix mapping: d0,d1 at (row=g, col=tq*2 .. +1); d2,d3 at row+8.
#define EPILOG_VARS() \
    const int lane = threadIdx.x & 31; \
    const int wid = threadIdx.x >> 5;  \
    const int wm = wid & 1;            \
    const int wn = wid >> 1;           \
    const int g = lane >> 2;           \
    const int tq = lane & 3;

// ---------------------------------------------------------------------------
// Kernel 0: transpose X[B,C,N] -> Xt[B,N,C]
// ---------------------------------------------------------------------------
__global__ __launch_bounds__(256) void transpose_kernel(const float* __restrict__ x)
{
    __shared__ float t[32][33];
    const int b = blockIdx.z;
    const int n0 = blockIdx.x * 32;
    const int c0 = blockIdx.y * 32;
    const int tx = threadIdx.x & 31;
    const int ty = threadIdx.x >> 5;
    const float* X = x + (size_t)b * CC * NN;
    float* Xt = g_xt + (size_t)b * NN * CC;
#pragma unroll
    for (int r = 0; r < 4; ++r)
        t[ty + r * 8][tx] = X[(size_t)(c0 + ty + r * 8) * NN + n0 + tx];
    __syncthreads();
#pragma unroll
    for (int r = 0; r < 4; ++r)
        Xt[(size_t)(n0 + ty + r * 8) * CC + c0 + tx] = t[tx][ty + r * 8];
}

// ---------------------------------------------------------------------------
// Kernel 1: QKV.
//  proj 0/1 (Q,K): D[n,d] = Xt·W^T + b  -> Qt/Kt[n,d] (cols d contiguous)
//  proj 2   (V):   D[d,n] = W·Xt^T + b  -> V[d,n]     (cols n contiguous)
// ---------------------------------------------------------------------------
__global__ __launch_bounds__(256) void qkv_kernel(
    const float* __restrict__ wq, const float* __restrict__ bq,
    const float* __restrict__ wk, const float* __restrict__ bk,
    const float* __restrict__ wv, const float* __restrict__ bv)
{
    __shared__ __nv_bfloat16 sAhi[128 * SMP], sAlo[128 * SMP];
    __shared__ __nv_bfloat16 sBhi[128 * SMP], sBlo[128 * SMP];

    const int z = blockIdx.z;
    const int b = z / 3, proj = z % 3;
    const float* W    = (proj == 0) ? wq : (proj == 1) ? wk : wv;
    const float* bias = (proj == 0) ? bq : (proj == 1) ? bk : bv;
    const float* Xt = g_xt + (size_t)b * NN * CC;

    float acc[4][4][4] = {};

    if (proj < 2) {
        const int n0 = blockIdx.x * 128;      // M = n
        const int d0 = blockIdx.y * 128;      // N = d
        gemm_core(Xt + (size_t)n0 * CC, CC, W + (size_t)d0 * CC, CC, CC / 32,
                  sAhi, sAlo, sBhi, sBlo, acc);
        EPILOG_VARS();
        float* dst = ((proj == 0) ? g_qt : g_kt) + (size_t)b * NN * CC;
#pragma unroll
        for (int mt = 0; mt < 4; ++mt) {
            const int n = n0 + wm * 64 + mt * 16 + g;
#pragma unroll
            for (int nt = 0; nt < 4; ++nt) {
                const int d = d0 + wn * 32 + nt * 8 + tq * 2;
                const float2 bb = *(const float2*)(bias + d);
                *(float2*)(dst + (size_t)n * CC + d) =
                    make_float2(acc[mt][nt][0] + bb.x, acc[mt][nt][1] + bb.y);
                *(float2*)(dst + (size_t)(n + 8) * CC + d) =
                    make_float2(acc[mt][nt][2] + bb.x, acc[mt][nt][3] + bb.y);
            }
        }
    } else {
        const int n0 = blockIdx.x * 128;      // N = n (positions)
        const int d0 = blockIdx.y * 128;      // M = d
        gemm_core(W + (size_t)d0 * CC, CC, Xt + (size_t)n0 * CC, CC, CC / 32,
                  sAhi, sAlo, sBhi, sBlo, acc);
        EPILOG_VARS();
        float* dst = g_v + (size_t)b * CC * NN;
#pragma unroll
        for (int mt = 0; mt < 4; ++mt) {
            const int d = d0 + wm * 64 + mt * 16 + g;
            const float b0 = bias[d], b1 = bias[d + 8];
#pragma unroll
            for (int nt = 0; nt < 4; ++nt) {
                const int n = n0 + wn * 32 + nt * 8 + tq * 2;
                *(float2*)(dst + (size_t)d * NN + n) =
                    make_float2(acc[mt][nt][0] + b0, acc[mt][nt][1] + b0);
                *(float2*)(dst + (size_t)(d + 8) * NN + n) =
                    make_float2(acc[mt][nt][2] + b1, acc[mt][nt][3] + b1);
            }
        }
    }
}

// ---------------------------------------------------------------------------
// Kernel 2: energy. D[i,j] = Qt·Kt^T -> E[i,j] (cols j contiguous)
// ---------------------------------------------------------------------------
__global__ __launch_bounds__(256) void energy_kernel()
{
    __shared__ __nv_bfloat16 sAhi[128 * SMP], sAlo[128 * SMP];
    __shared__ __nv_bfloat16 sBhi[128 * SMP], sBlo[128 * SMP];

    const int b = blockIdx.z;
    const int i0 = blockIdx.y * 128;
    const int j0 = blockIdx.x * 128;
    const float* Qt = g_qt + ((size_t)b * NN + i0) * CC;
    const float* Kt = g_kt + ((size_t)b * NN + j0) * CC;

    float acc[4][4][4] = {};
    gemm_core(Qt, CC, Kt, CC, CC / 32, sAhi, sAlo, sBhi, sBlo, acc);

    EPILOG_VARS();
    float* E = g_e + (size_t)b * NN * NN;
#pragma unroll
    for (int mt = 0; mt < 4; ++mt) {
        const int i = i0 + wm * 64 + mt * 16 + g;
#pragma unroll
        for (int nt = 0; nt < 4; ++nt) {
            const int j = j0 + wn * 32 + nt * 8 + tq * 2;
            *(float2*)(E + (size_t)i * NN + j) = make_float2(acc[mt][nt][0], acc[mt][nt][1]);
            *(float2*)(E + (size_t)(i + 8) * NN + j) = make_float2(acc[mt][nt][2], acc[mt][nt][3]);
        }
    }
}

// ---------------------------------------------------------------------------
// Kernel 3: row softmax (in place on g_e)
// ---------------------------------------------------------------------------
__global__ __launch_bounds__(256) void softmax_kernel()
{
    const size_t row = blockIdx.x;
    float* p = g_e + row * (size_t)NN;
    const int tid = threadIdx.x;

    float4 v[4];
    float mx = -1e30f;
#pragma unroll
    for (int t = 0; t < 4; ++t) {
        v[t] = ((const float4*)p)[tid + t * 256];
        mx = fmaxf(mx, fmaxf(fmaxf(v[t].x, v[t].y), fmaxf(v[t].z, v[t].w)));
    }
    __shared__ float red[8];
#pragma unroll
    for (int o = 16; o > 0; o >>= 1) mx = fmaxf(mx, __shfl_xor_sync(0xffffffffu, mx, o));
    if ((tid & 31) == 0) red[tid >> 5] = mx;
    __syncthreads();
    mx = red[0];
#pragma unroll
    for (int w = 1; w < 8; ++w) mx = fmaxf(mx, red[w]);
    __syncthreads();

    float sum = 0.f;
#pragma unroll
    for (int t = 0; t < 4; ++t) {
        v[t].x = __expf(v[t].x - mx); v[t].y = __expf(v[t].y - mx);
        v[t].z = __expf(v[t].z - mx); v[t].w = __expf(v[t].w - mx);
        sum += v[t].x + v[t].y + v[t].z + v[t].w;
    }
#pragma unroll
    for (int o = 16; o > 0; o >>= 1) sum += __shfl_xor_sync(0xffffffffu, sum, o);
    if ((tid & 31) == 0) red[tid >> 5] = sum;
    __syncthreads();
    sum = 0.f;
#pragma unroll
    for (int w = 0; w < 8; ++w) sum += red[w];

    const float inv = 1.0f / sum;
#pragma unroll
    for (int t = 0; t < 4; ++t) {
        v[t].x *= inv; v[t].y *= inv; v[t].z *= inv; v[t].w *= inv;
        ((float4*)p)[tid + t * 256] = v[t];
    }
}

// ---------------------------------------------------------------------------
// Kernel 4: VA + residual. D[c,i] = V·P^T -> out[c,i] (cols i contiguous)
// ---------------------------------------------------------------------------
__global__ __launch_bounds__(256) void va_kernel(
    const float* __restrict__ pose, const float* __restrict__ gamma,
    float* __restrict__ out)
{
    __shared__ __nv_bfloat16 sAhi[128 * SMP], sAlo[128 * SMP];
    __shared__ __nv_bfloat16 sBhi[128 * SMP], sBlo[128 * SMP];

    const int b = blockIdx.z;
    const int c0 = blockIdx.y * 128;      // M = c
    const int i0 = blockIdx.x * 128;      // N = i
    const float* V = g_v + ((size_t)b * CC + c0) * NN;
    const float* P = g_e + ((size_t)b * NN + i0) * NN;

    float acc[4][4][4] = {};
    gemm_core(V, NN, P, NN, NN / 32, sAhi, sAlo, sBhi, sBlo, acc);

    EPILOG_VARS();
    const float gm = gamma[0];
#pragma unroll
    for (int mt = 0; mt < 4; ++mt) {
        const int c = c0 + wm * 64 + mt * 16 + g;
#pragma unroll
        for (int nt = 0; nt < 4; ++nt) {
            const int i = i0 + wn * 32 + nt * 8 + tq * 2;
            const size_t i1 = ((size_t)b * CC + c) * NN + i;
            const size_t i2 = ((size_t)b * CC + c + 8) * NN + i;
            float2 p1 = *(const float2*)(pose + i1);
            float2 p2 = *(const float2*)(pose + i2);
            *(float2*)(out + i1) = make_float2(fmaf(gm, acc[mt][nt][0], p1.x),
                                               fmaf(gm, acc[mt][nt][1], p1.y));
            *(float2*)(out + i2) = make_float2(fmaf(gm, acc[mt][nt][2], p2.x),
                                               fmaf(gm, acc[mt][nt][3], p2.y));
        }
    }
}

// ---------------------------------------------------------------------------
extern "C" void kernel_launch(void* const* d_in, const int* in_sizes, int n_in,
                              void* d_out, int out_size)
{
    const float* pose  = (const float*)d_in[0];
    const float* wq    = (const float*)d_in[1];
    const float* bq    = (const float*)d_in[2];
    const float* wk    = (const float*)d_in[3];
    const float* bk    = (const float*)d_in[4];
    const float* wv    = (const float*)d_in[5];
    const float* bv    = (const float*)d_in[6];
    const float* gamma = (const float*)d_in[7];
    float* out = (float*)d_out;

    transpose_kernel<<<dim3(NN / 32, CC / 32, BB), 256>>>(pose);
    qkv_kernel      <<<dim3(NN / 128, CC / 128, 3 * BB), 256>>>(wq, bq, wk, bk, wv, bv);
    energy_kernel   <<<dim3(NN / 128, NN / 128, BB), 256>>>();
    softmax_kernel  <<<dim3(BB * NN), 256>>>();
    va_kernel       <<<dim3(NN / 128, CC / 128, BB), 256>>>(pose, gamma, out);
}

// round 7
// speedup vs baseline: 2.4430x; 1.0207x over previous
#include <cuda_runtime.h>
#include <cuda_bf16.h>
#include <cstdint>

#define BB 4
#define CC 256
#define NN 4096

// ---------------- scratch (__device__ globals; allocation-free rule) -------
__device__ __nv_bfloat16 g_xth[BB * NN * CC], g_xtl[BB * NN * CC];   // Xt [B,N,C]
__device__ __nv_bfloat16 g_qth[BB * NN * CC], g_qtl[BB * NN * CC];   // Qt [B,N,C]
__device__ __nv_bfloat16 g_kth[BB * NN * CC], g_ktl[BB * NN * CC];   // Kt [B,N,C]
__device__ __nv_bfloat16 g_vh [BB * CC * NN], g_vl [BB * CC * NN];   // V  [B,C,N]
__device__ __nv_bfloat16 g_wh [3 * CC * CC],  g_wl [3 * CC * CC];    // W split
__device__ float         g_e  [(size_t)BB * NN * NN];                // E fp32
__device__ __nv_bfloat16 g_ph [(size_t)BB * NN * NN];                // P hi
__device__ __nv_bfloat16 g_pl [(size_t)BB * NN * NN];                // P lo

// Pipelined GEMM: block 128x128, BK=16, 3 cp.async stages, 48KB static smem.
// Tile = 128 rows x 16 bf16 = 32B/row = 2x16B chunks; swizzle chunk^=(row>>2)&1.
#define TILE_B   4096
#define STAGE_B  (4 * TILE_B)        // Ahi, Alo, Bhi, Blo
#define NSTAGE   3
#define SMEM_TOT (NSTAGE * STAGE_B)  // 49152 = 48KB static (no opt-in needed)

static __device__ __forceinline__ uint32_t smem_u32(const void* p) {
    uint32_t a;
    asm("{ .reg .u64 t; cvta.to.shared.u64 t, %1; cvt.u32.u64 %0, t; }" : "=r"(a) : "l"(p));
    return a;
}
static __device__ __forceinline__ void cp16(uint32_t dst, const void* src) {
    asm volatile("cp.async.cg.shared.global [%0], [%1], 16;" :: "r"(dst), "l"(src));
}
static __device__ __forceinline__ void ldmx4(uint32_t& r0, uint32_t& r1, uint32_t& r2,
                                             uint32_t& r3, uint32_t addr) {
    asm volatile("ldmatrix.sync.aligned.m8n8.x4.shared.b16 {%0,%1,%2,%3}, [%4];"
                 : "=r"(r0), "=r"(r1), "=r"(r2), "=r"(r3) : "r"(addr));
}
static __device__ __forceinline__ void ldmx2(uint32_t& r0, uint32_t& r1, uint32_t addr) {
    asm volatile("ldmatrix.sync.aligned.m8n8.x2.shared.b16 {%0,%1}, [%2];"
                 : "=r"(r0), "=r"(r1) : "r"(addr));
}
static __device__ __forceinline__ void mma16816(float* d, uint32_t a0, uint32_t a1,
                                                uint32_t a2, uint32_t a3,
                                                uint32_t b0, uint32_t b1) {
    asm volatile(
        "mma.sync.aligned.m16n8k16.row.col.f32.bf16.bf16.f32 "
        "{%0,%1,%2,%3}, {%4,%5,%6,%7}, {%8,%9}, {%0,%1,%2,%3};"
        : "+f"(d[0]), "+f"(d[1]), "+f"(d[2]), "+f"(d[3])
        : "r"(a0), "r"(a1), "r"(a2), "r"(a3), "r"(b0), "r"(b1));
}
static __device__ __forceinline__ void split2(float x, float y,
                                              __nv_bfloat162& h, __nv_bfloat162& l) {
    h = __floats2bfloat162_rn(x, y);
    float2 f = __bfloat1622float2(h);
    l = __floats2bfloat162_rn(x - f.x, y - f.y);
}

// ---------------------------------------------------------------------------
// cp.async producer: one 128x16 stage (A hi/lo + B hi/lo).
// 256 threads: row = tid>>1, chunk = tid&1; one cp16 per tile.
// ---------------------------------------------------------------------------
static __device__ __forceinline__ void issue_stage(
    const __nv_bfloat16* __restrict__ Ahi, const __nv_bfloat16* __restrict__ Alo, int lda,
    const __nv_bfloat16* __restrict__ Bhi, const __nv_bfloat16* __restrict__ Blo, int ldb,
    int k0, uint32_t st, int tid)
{
    const int row = tid >> 1;
    const int chunk = tid & 1;
    const uint32_t dsto = row * 32 + ((chunk ^ ((row >> 2) & 1)) * 16);
    const size_t asrc = (size_t)row * lda + k0 + chunk * 8;
    const size_t bsrc = (size_t)row * ldb + k0 + chunk * 8;
    cp16(st + dsto,              Ahi + asrc);
    cp16(st + TILE_B + dsto,     Alo + asrc);
    cp16(st + 2 * TILE_B + dsto, Bhi + bsrc);
    cp16(st + 3 * TILE_B + dsto, Blo + bsrc);
}

// ---------------------------------------------------------------------------
// Consumer: one BK=16 stage. warp grid 2(m) x 4(n), warp tile 64x32.
// 3-term split: Ah*Bh + Ah*Bl + Al*Bh.
// ---------------------------------------------------------------------------
static __device__ __forceinline__ void compute_stage(
    uint32_t st, int lane, int wm, int wn, float acc[4][4][4])
{
    const uint32_t parA = ((lane & 15) >> 2) & 1;
    const uint32_t parB = ((lane & 7) >> 2) & 1;
    const uint32_t rowA = wm * 64 + (lane & 15);
    const uint32_t rowB = wn * 32 + (lane & 7);
    const uint32_t cA = ((lane >> 4) & 1) ^ parA;
    const uint32_t cB = ((lane >> 3) & 1) ^ parB;

    uint32_t bh[4][2], bl[4][2];
#pragma unroll
    for (int nt = 0; nt < 4; ++nt) {
        const uint32_t bo = (rowB + nt * 8) * 32 + cB * 16;
        ldmx2(bh[nt][0], bh[nt][1], st + 2 * TILE_B + bo);
        ldmx2(bl[nt][0], bl[nt][1], st + 3 * TILE_B + bo);
    }
#pragma unroll
    for (int mt = 0; mt < 4; ++mt) {
        const uint32_t ao = (rowA + mt * 16) * 32 + cA * 16;
        uint32_t ah0, ah1, ah2, ah3, al0, al1, al2, al3;
        ldmx4(ah0, ah1, ah2, ah3, st + ao);
        ldmx4(al0, al1, al2, al3, st + TILE_B + ao);
#pragma unroll
        for (int nt = 0; nt < 4; ++nt) {
            mma16816(acc[mt][nt], ah0, ah1, ah2, ah3, bh[nt][0], bh[nt][1]);
            mma16816(acc[mt][nt], ah0, ah1, ah2, ah3, bl[nt][0], bl[nt][1]);
            mma16816(acc[mt][nt], al0, al1, al2, al3, bh[nt][0], bh[nt][1]);
        }
    }
}

static __device__ __forceinline__ void gemm_bf16(
    const __nv_bfloat16* __restrict__ Ahi, const __nv_bfloat16* __restrict__ Alo, int lda,
    const __nv_bfloat16* __restrict__ Bhi, const __nv_bfloat16* __restrict__ Blo, int ldb,
    int kiters, char* smem, float acc[4][4][4])
{
    const int tid = threadIdx.x;
    const int lane = tid & 31, wid = tid >> 5;
    const int wm = wid & 1, wn = wid >> 1;
    const uint32_t sb = smem_u32(smem);

    issue_stage(Ahi, Alo, lda, Bhi, Blo, ldb, 0, sb, tid);
    asm volatile("cp.async.commit_group;" ::: "memory");
    issue_stage(Ahi, Alo, lda, Bhi, Blo, ldb, 16, sb + STAGE_B, tid);
    asm volatile("cp.async.commit_group;" ::: "memory");

    int nbuf = 2;   // next buffer index (mod 3)
    for (int kb = 0; kb < kiters; ++kb) {
        if (kb + 2 < kiters)
            issue_stage(Ahi, Alo, lda, Bhi, Blo, ldb, (kb + 2) * 16,
                        sb + nbuf * STAGE_B, tid);
        asm volatile("cp.async.commit_group;" ::: "memory");
        asm volatile("cp.async.wait_group 2;" ::: "memory");
        __syncthreads();
        const int cbuf = (nbuf + 1) % 3;   // == kb % 3
        compute_stage(sb + cbuf * STAGE_B, lane, wm, wn, acc);
        __syncthreads();
        nbuf = cbuf;
    }
}

// Fragment mapping: d0,d1 at (row g, col tq*2..+1); d2,d3 at row g+8.
#define EPILOG_VARS() \
    const int lane = threadIdx.x & 31; \
    const int wid = threadIdx.x >> 5;  \
    const int wm = wid & 1;            \
    const int wn = wid >> 1;           \
    const int g = lane >> 2;           \
    const int tq = lane & 3;

// ---------------------------------------------------------------------------
// Kernel 0a: split weights fp32 -> bf16 hi/lo
// ---------------------------------------------------------------------------
__global__ __launch_bounds__(256) void wsplit_kernel(
    const float* __restrict__ wq, const float* __restrict__ wk,
    const float* __restrict__ wv)
{
    const int idx = blockIdx.x * 256 + threadIdx.x;
    const int which = idx / (CC * CC);
    const int off = idx % (CC * CC);
    const float* src = (which == 0) ? wq : (which == 1) ? wk : wv;
    float v = src[off];
    __nv_bfloat16 h = __float2bfloat16(v);
    g_wh[idx] = h;
    g_wl[idx] = __float2bfloat16(v - __bfloat162float(h));
}

// ---------------------------------------------------------------------------
// Kernel 0b: transpose+split X[B,C,N] -> Xt hi/lo [B,N,C]
// ---------------------------------------------------------------------------
__global__ __launch_bounds__(256) void transpose_kernel(const float* __restrict__ x)
{
    __shared__ float t[32][33];
    const int b = blockIdx.z;
    const int n0 = blockIdx.x * 32;
    const int c0 = blockIdx.y * 32;
    const int tx = threadIdx.x & 31;
    const int ty = threadIdx.x >> 5;
    const float* X = x + (size_t)b * CC * NN;
    __nv_bfloat16* Xh = g_xth + (size_t)b * NN * CC;
    __nv_bfloat16* Xl = g_xtl + (size_t)b * NN * CC;
#pragma unroll
    for (int r = 0; r < 4; ++r)
        t[ty + r * 8][tx] = X[(size_t)(c0 + ty + r * 8) * NN + n0 + tx];
    __syncthreads();
#pragma unroll
    for (int r = 0; r < 4; ++r) {
        float v = t[tx][ty + r * 8];
        __nv_bfloat16 h = __float2bfloat16(v);
        const size_t o = (size_t)(n0 + ty + r * 8) * CC + c0 + tx;
        Xh[o] = h;
        Xl[o] = __float2bfloat16(v - __bfloat162float(h));
    }
}

// ---------------------------------------------------------------------------
// Kernel 1: QKV.  proj 0/1: D[n,d]=Xt·W^T+b -> Qt/Kt hi/lo [n,d]
//                 proj 2:   D[d,n]=W·Xt^T+b -> V hi/lo [d,n]
// ---------------------------------------------------------------------------
__global__ __launch_bounds__(256) void qkv_kernel(
    const float* __restrict__ bq, const float* __restrict__ bk,
    const float* __restrict__ bv)
{
    __shared__ __align__(16) char smem[SMEM_TOT];
    const int z = blockIdx.z;
    const int b = z / 3, proj = z % 3;
    const float* bias = (proj == 0) ? bq : (proj == 1) ? bk : bv;
    const __nv_bfloat16* Wh = g_wh + (size_t)proj * CC * CC;
    const __nv_bfloat16* Wl = g_wl + (size_t)proj * CC * CC;
    const __nv_bfloat16* Xh = g_xth + (size_t)b * NN * CC;
    const __nv_bfloat16* Xl = g_xtl + (size_t)b * NN * CC;

    float acc[4][4][4] = {};

    if (proj < 2) {
        const int n0 = blockIdx.x * 128;
        const int d0 = blockIdx.y * 128;
        gemm_bf16(Xh + (size_t)n0 * CC, Xl + (size_t)n0 * CC, CC,
                  Wh + (size_t)d0 * CC, Wl + (size_t)d0 * CC, CC,
                  CC / 16, smem, acc);
        EPILOG_VARS();
        __nv_bfloat16* dh = ((proj == 0) ? g_qth : g_kth) + (size_t)b * NN * CC;
        __nv_bfloat16* dl = ((proj == 0) ? g_qtl : g_ktl) + (size_t)b * NN * CC;
#pragma unroll
        for (int mt = 0; mt < 4; ++mt) {
            const int n = n0 + wm * 64 + mt * 16 + g;
#pragma unroll
            for (int nt = 0; nt < 4; ++nt) {
                const int d = d0 + wn * 32 + nt * 8 + tq * 2;
                const float2 bb = *(const float2*)(bias + d);
                __nv_bfloat162 h, l;
                split2(acc[mt][nt][0] + bb.x, acc[mt][nt][1] + bb.y, h, l);
                *(__nv_bfloat162*)(dh + (size_t)n * CC + d) = h;
                *(__nv_bfloat162*)(dl + (size_t)n * CC + d) = l;
                split2(acc[mt][nt][2] + bb.x, acc[mt][nt][3] + bb.y, h, l);
                *(__nv_bfloat162*)(dh + (size_t)(n + 8) * CC + d) = h;
                *(__nv_bfloat162*)(dl + (size_t)(n + 8) * CC + d) = l;
            }
        }
    } else {
        const int n0 = blockIdx.x * 128;
        const int d0 = blockIdx.y * 128;
        gemm_bf16(Wh + (size_t)d0 * CC, Wl + (size_t)d0 * CC, CC,
                  Xh + (size_t)n0 * CC, Xl + (size_t)n0 * CC, CC,
                  CC / 16, smem, acc);
        EPILOG_VARS();
        __nv_bfloat16* dh = g_vh + (size_t)b * CC * NN;
        __nv_bfloat16* dl = g_vl + (size_t)b * CC * NN;
#pragma unroll
        for (int mt = 0; mt < 4; ++mt) {
            const int d = d0 + wm * 64 + mt * 16 + g;
            const float b0 = bias[d], b1 = bias[d + 8];
#pragma unroll
            for (int nt = 0; nt < 4; ++nt) {
                const int n = n0 + wn * 32 + nt * 8 + tq * 2;
                __nv_bfloat162 h, l;
                split2(acc[mt][nt][0] + b0, acc[mt][nt][1] + b0, h, l);
                *(__nv_bfloat162*)(dh + (size_t)d * NN + n) = h;
                *(__nv_bfloat162*)(dl + (size_t)d * NN + n) = l;
                split2(acc[mt][nt][2] + b1, acc[mt][nt][3] + b1, h, l);
                *(__nv_bfloat162*)(dh + (size_t)(d + 8) * NN + n) = h;
                *(__nv_bfloat162*)(dl + (size_t)(d + 8) * NN + n) = l;
            }
        }
    }
}

// ---------------------------------------------------------------------------
// Kernel 2: energy. D[i,j] = Qt·Kt^T -> E fp32 [i,j]
// ---------------------------------------------------------------------------
__global__ __launch_bounds__(256) void energy_kernel()
{
    __shared__ __align__(16) char smem[SMEM_TOT];
    const int b = blockIdx.z;
    const int i0 = blockIdx.y * 128;
    const int j0 = blockIdx.x * 128;

    float acc[4][4][4] = {};
    gemm_bf16(g_qth + ((size_t)b * NN + i0) * CC, g_qtl + ((size_t)b * NN + i0) * CC, CC,
              g_kth + ((size_t)b * NN + j0) * CC, g_ktl + ((size_t)b * NN + j0) * CC, CC,
              CC / 16, smem, acc);

    EPILOG_VARS();
    float* E = g_e + (size_t)b * NN * NN;
#pragma unroll
    for (int mt = 0; mt < 4; ++mt) {
        const int i = i0 + wm * 64 + mt * 16 + g;
#pragma unroll
        for (int nt = 0; nt < 4; ++nt) {
            const int j = j0 + wn * 32 + nt * 8 + tq * 2;
            *(float2*)(E + (size_t)i * NN + j) = make_float2(acc[mt][nt][0], acc[mt][nt][1]);
            *(float2*)(E + (size_t)(i + 8) * NN + j) = make_float2(acc[mt][nt][2], acc[mt][nt][3]);
        }
    }
}

// ---------------------------------------------------------------------------
// Kernel 3: row softmax, E fp32 -> P hi/lo bf16
// ---------------------------------------------------------------------------
__global__ __launch_bounds__(256) void softmax_kernel()
{
    const size_t row = blockIdx.x;
    const float* p = g_e + row * (size_t)NN;
    __nv_bfloat162* ph = (__nv_bfloat162*)(g_ph + row * (size_t)NN);
    __nv_bfloat162* pl = (__nv_bfloat162*)(g_pl + row * (size_t)NN);
    const int tid = threadIdx.x;

    float4 v[4];
    float mx = -1e30f;
#pragma unroll
    for (int t = 0; t < 4; ++t) {
        v[t] = ((const float4*)p)[tid + t * 256];
        mx = fmaxf(mx, fmaxf(fmaxf(v[t].x, v[t].y), fmaxf(v[t].z, v[t].w)));
    }
    __shared__ float red[8];
#pragma unroll
    for (int o = 16; o > 0; o >>= 1) mx = fmaxf(mx, __shfl_xor_sync(0xffffffffu, mx, o));
    if ((tid & 31) == 0) red[tid >> 5] = mx;
    __syncthreads();
    mx = red[0];
#pragma unroll
    for (int w = 1; w < 8; ++w) mx = fmaxf(mx, red[w]);
    __syncthreads();

    float sum = 0.f;
#pragma unroll
    for (int t = 0; t < 4; ++t) {
        v[t].x = __expf(v[t].x - mx); v[t].y = __expf(v[t].y - mx);
        v[t].z = __expf(v[t].z - mx); v[t].w = __expf(v[t].w - mx);
        sum += v[t].x + v[t].y + v[t].z + v[t].w;
    }
#pragma unroll
    for (int o = 16; o > 0; o >>= 1) sum += __shfl_xor_sync(0xffffffffu, sum, o);
    if ((tid & 31) == 0) red[tid >> 5] = sum;
    __syncthreads();
    sum = 0.f;
#pragma unroll
    for (int w = 0; w < 8; ++w) sum += red[w];

    const float inv = 1.0f / sum;
#pragma unroll
    for (int t = 0; t < 4; ++t) {
        const int o2 = (tid + t * 256) * 2;
        __nv_bfloat162 h, l;
        split2(v[t].x * inv, v[t].y * inv, h, l);
        ph[o2] = h; pl[o2] = l;
        split2(v[t].z * inv, v[t].w * inv, h, l);
        ph[o2 + 1] = h; pl[o2 + 1] = l;
    }
}

// ---------------------------------------------------------------------------
// Kernel 4: VA + residual. D[c,i] = V·P^T -> out[c,i]
// ---------------------------------------------------------------------------
__global__ __launch_bounds__(256) void va_kernel(
    const float* __restrict__ pose, const float* __restrict__ gamma,
    float* __restrict__ out)
{
    __shared__ __align__(16) char smem[SMEM_TOT];
    const int b = blockIdx.z;
    const int c0 = blockIdx.y * 128;
    const int i0 = blockIdx.x * 128;

    float acc[4][4][4] = {};
    gemm_bf16(g_vh + ((size_t)b * CC + c0) * NN, g_vl + ((size_t)b * CC + c0) * NN, NN,
              g_ph + ((size_t)b * NN + i0) * NN, g_pl + ((size_t)b * NN + i0) * NN, NN,
              NN / 16, smem, acc);

    EPILOG_VARS();
    const float gm = gamma[0];
#pragma unroll
    for (int mt = 0; mt < 4; ++mt) {
        const int c = c0 + wm * 64 + mt * 16 + g;
#pragma unroll
        for (int nt = 0; nt < 4; ++nt) {
            const int i = i0 + wn * 32 + nt * 8 + tq * 2;
            const size_t i1 = ((size_t)b * CC + c) * NN + i;
            const size_t i2 = ((size_t)b * CC + c + 8) * NN + i;
            float2 p1 = *(const float2*)(pose + i1);
            float2 p2 = *(const float2*)(pose + i2);
            *(float2*)(out + i1) = make_float2(fmaf(gm, acc[mt][nt][0], p1.x),
                                               fmaf(gm, acc[mt][nt][1], p1.y));
            *(float2*)(out + i2) = make_float2(fmaf(gm, acc[mt][nt][2], p2.x),
                                               fmaf(gm, acc[mt][nt][3], p2.y));
        }
    }
}

// ---------------------------------------------------------------------------
extern "C" void kernel_launch(void* const* d_in, const int* in_sizes, int n_in,
                              void* d_out, int out_size)
{
    const float* pose  = (const float*)d_in[0];
    const float* wq    = (const float*)d_in[1];
    const float* bq    = (const float*)d_in[2];
    const float* wk    = (const float*)d_in[3];
    const float* bk    = (const float*)d_in[4];
    const float* wv    = (const float*)d_in[5];
    const float* bv    = (const float*)d_in[6];
    const float* gamma = (const float*)d_in[7];
    float* out = (float*)d_out;

    wsplit_kernel   <<<3 * CC * CC / 256, 256>>>(wq, wk, wv);
    transpose_kernel<<<dim3(NN / 32, CC / 32, BB), 256>>>(pose);
    qkv_kernel      <<<dim3(NN / 128, CC / 128, 3 * BB), 256>>>(bq, bk, bv);
    energy_kernel   <<<dim3(NN / 128, NN / 128, BB), 256>>>();
    softmax_kernel  <<<dim3(BB * NN), 256>>>();
    va_kernel       <<<dim3(NN / 128, CC / 128, BB), 256>>>(pose, gamma, out);
}

// round 8
// speedup vs baseline: 3.4897x; 1.4284x over previous
#include <cuda_runtime.h>
#include <cuda_bf16.h>
#include <cstdint>

#define BB 4
#define CC 256
#define NN 4096

// ---------------- scratch (__device__ globals; allocation-free rule) -------
__device__ __nv_bfloat16 g_xth[BB * NN * CC], g_xtl[BB * NN * CC];   // Xt [B,N,C]
__device__ __nv_bfloat16 g_qth[BB * NN * CC], g_qtl[BB * NN * CC];   // Qt [B,N,C]
__device__ __nv_bfloat16 g_kth[BB * NN * CC], g_ktl[BB * NN * CC];   // Kt [B,N,C]
__device__ __nv_bfloat16 g_vh [BB * CC * NN];                        // V  [B,C,N] (hi only)
__device__ __nv_bfloat16 g_wh [3 * CC * CC],  g_wl [3 * CC * CC];    // W split
__device__ float         g_e  [(size_t)BB * NN * NN];                // E fp32
__device__ __nv_bfloat16 g_ph [(size_t)BB * NN * NN];                // P hi only

// Tile = 128 rows x 16 bf16 = 32B/row = 2x16B chunks; swizzle chunk^=(row>>2)&1.
#define TILE_B    4096
#define STAGE3_B  (4 * TILE_B)   // Ahi, Alo, Bhi, Blo  (3-term path)
#define STAGE1_B  (2 * TILE_B)   // Ah, Bh              (1-term path)
#define SMEM_TOT  32768          // 2 x STAGE3_B == 4 x STAGE1_B

static __device__ __forceinline__ uint32_t smem_u32(const void* p) {
    uint32_t a;
    asm("{ .reg .u64 t; cvta.to.shared.u64 t, %1; cvt.u32.u64 %0, t; }" : "=r"(a) : "l"(p));
    return a;
}
static __device__ __forceinline__ void cp16(uint32_t dst, const void* src) {
    asm volatile("cp.async.cg.shared.global [%0], [%1], 16;" :: "r"(dst), "l"(src));
}
static __device__ __forceinline__ void ldmx4(uint32_t& r0, uint32_t& r1, uint32_t& r2,
                                             uint32_t& r3, uint32_t addr) {
    asm volatile("ldmatrix.sync.aligned.m8n8.x4.shared.b16 {%0,%1,%2,%3}, [%4];"
                 : "=r"(r0), "=r"(r1), "=r"(r2), "=r"(r3) : "r"(addr));
}
static __device__ __forceinline__ void ldmx2(uint32_t& r0, uint32_t& r1, uint32_t addr) {
    asm volatile("ldmatrix.sync.aligned.m8n8.x2.shared.b16 {%0,%1}, [%2];"
                 : "=r"(r0), "=r"(r1) : "r"(addr));
}
static __device__ __forceinline__ void mma16816(float* d, uint32_t a0, uint32_t a1,
                                                uint32_t a2, uint32_t a3,
                                                uint32_t b0, uint32_t b1) {
    asm volatile(
        "mma.sync.aligned.m16n8k16.row.col.f32.bf16.bf16.f32 "
        "{%0,%1,%2,%3}, {%4,%5,%6,%7}, {%8,%9}, {%0,%1,%2,%3};"
        : "+f"(d[0]), "+f"(d[1]), "+f"(d[2]), "+f"(d[3])
        : "r"(a0), "r"(a1), "r"(a2), "r"(a3), "r"(b0), "r"(b1));
}
static __device__ __forceinline__ void split2(float x, float y,
                                              __nv_bfloat162& h, __nv_bfloat162& l) {
    h = __floats2bfloat162_rn(x, y);
    float2 f = __bfloat1622float2(h);
    l = __floats2bfloat162_rn(x - f.x, y - f.y);
}

// ---------------------- 3-term pipeline (2 stages) -------------------------
static __device__ __forceinline__ void issue3(
    const __nv_bfloat16* __restrict__ Ahi, const __nv_bfloat16* __restrict__ Alo, int lda,
    const __nv_bfloat16* __restrict__ Bhi, const __nv_bfloat16* __restrict__ Blo, int ldb,
    int k0, uint32_t st, int tid)
{
    const int row = tid >> 1;
    const int chunk = tid & 1;
    const uint32_t dsto = row * 32 + ((chunk ^ ((row >> 2) & 1)) * 16);
    const size_t asrc = (size_t)row * lda + k0 + chunk * 8;
    const size_t bsrc = (size_t)row * ldb + k0 + chunk * 8;
    cp16(st + dsto,              Ahi + asrc);
    cp16(st + TILE_B + dsto,     Alo + asrc);
    cp16(st + 2 * TILE_B + dsto, Bhi + bsrc);
    cp16(st + 3 * TILE_B + dsto, Blo + bsrc);
}

static __device__ __forceinline__ void compute3(
    uint32_t st, int lane, int wm, int wn, float acc[4][4][4])
{
    const uint32_t rowA = wm * 64 + (lane & 15);
    const uint32_t rowB = wn * 32 + (lane & 7);
    const uint32_t cA = ((lane >> 4) & 1) ^ (((lane & 15) >> 2) & 1);
    const uint32_t cB = ((lane >> 3) & 1) ^ (((lane & 7) >> 2) & 1);

    uint32_t bh[4][2], bl[4][2];
#pragma unroll
    for (int nt = 0; nt < 4; ++nt) {
        const uint32_t bo = (rowB + nt * 8) * 32 + cB * 16;
        ldmx2(bh[nt][0], bh[nt][1], st + 2 * TILE_B + bo);
        ldmx2(bl[nt][0], bl[nt][1], st + 3 * TILE_B + bo);
    }
#pragma unroll
    for (int mt = 0; mt < 4; ++mt) {
        const uint32_t ao = (rowA + mt * 16) * 32 + cA * 16;
        uint32_t ah0, ah1, ah2, ah3, al0, al1, al2, al3;
        ldmx4(ah0, ah1, ah2, ah3, st + ao);
        ldmx4(al0, al1, al2, al3, st + TILE_B + ao);
#pragma unroll
        for (int nt = 0; nt < 4; ++nt) {
            mma16816(acc[mt][nt], ah0, ah1, ah2, ah3, bh[nt][0], bh[nt][1]);
            mma16816(acc[mt][nt], ah0, ah1, ah2, ah3, bl[nt][0], bl[nt][1]);
            mma16816(acc[mt][nt], al0, al1, al2, al3, bh[nt][0], bh[nt][1]);
        }
    }
}

static __device__ __forceinline__ void gemm3(
    const __nv_bfloat16* __restrict__ Ahi, const __nv_bfloat16* __restrict__ Alo, int lda,
    const __nv_bfloat16* __restrict__ Bhi, const __nv_bfloat16* __restrict__ Blo, int ldb,
    int kiters, char* smem, float acc[4][4][4])
{
    const int tid = threadIdx.x;
    const int lane = tid & 31, wid = tid >> 5;
    const int wm = wid & 1, wn = wid >> 1;
    const uint32_t sb = smem_u32(smem);

    issue3(Ahi, Alo, lda, Bhi, Blo, ldb, 0, sb, tid);
    asm volatile("cp.async.commit_group;" ::: "memory");
    for (int kb = 0; kb < kiters; ++kb) {
        if (kb + 1 < kiters)
            issue3(Ahi, Alo, lda, Bhi, Blo, ldb, (kb + 1) * 16,
                   sb + ((kb + 1) & 1) * STAGE3_B, tid);
        asm volatile("cp.async.commit_group;" ::: "memory");
        asm volatile("cp.async.wait_group 1;" ::: "memory");
        __syncthreads();
        compute3(sb + (kb & 1) * STAGE3_B, lane, wm, wn, acc);
        __syncthreads();
    }
}

// ---------------------- 1-term pipeline (4 stages) -------------------------
static __device__ __forceinline__ void issue1(
    const __nv_bfloat16* __restrict__ Ah, int lda,
    const __nv_bfloat16* __restrict__ Bh, int ldb,
    int k0, uint32_t st, int tid)
{
    const int row = tid >> 1;
    const int chunk = tid & 1;
    const uint32_t dsto = row * 32 + ((chunk ^ ((row >> 2) & 1)) * 16);
    cp16(st + dsto,          Ah + (size_t)row * lda + k0 + chunk * 8);
    cp16(st + TILE_B + dsto, Bh + (size_t)row * ldb + k0 + chunk * 8);
}

static __device__ __forceinline__ void compute1(
    uint32_t st, int lane, int wm, int wn, float acc[4][4][4])
{
    const uint32_t rowA = wm * 64 + (lane & 15);
    const uint32_t rowB = wn * 32 + (lane & 7);
    const uint32_t cA = ((lane >> 4) & 1) ^ (((lane & 15) >> 2) & 1);
    const uint32_t cB = ((lane >> 3) & 1) ^ (((lane & 7) >> 2) & 1);

    uint32_t bh[4][2];
#pragma unroll
    for (int nt = 0; nt < 4; ++nt) {
        const uint32_t bo = (rowB + nt * 8) * 32 + cB * 16;
        ldmx2(bh[nt][0], bh[nt][1], st + TILE_B + bo);
    }
#pragma unroll
    for (int mt = 0; mt < 4; ++mt) {
        const uint32_t ao = (rowA + mt * 16) * 32 + cA * 16;
        uint32_t a0, a1, a2, a3;
        ldmx4(a0, a1, a2, a3, st + ao);
#pragma unroll
        for (int nt = 0; nt < 4; ++nt)
            mma16816(acc[mt][nt], a0, a1, a2, a3, bh[nt][0], bh[nt][1]);
    }
}

static __device__ __forceinline__ void gemm1(
    const __nv_bfloat16* __restrict__ Ah, int lda,
    const __nv_bfloat16* __restrict__ Bh, int ldb,
    int kiters, char* smem, float acc[4][4][4])
{
    const int tid = threadIdx.x;
    const int lane = tid & 31, wid = tid >> 5;
    const int wm = wid & 1, wn = wid >> 1;
    const uint32_t sb = smem_u32(smem);

#pragma unroll
    for (int s = 0; s < 3; ++s) {
        issue1(Ah, lda, Bh, ldb, s * 16, sb + s * STAGE1_B, tid);
        asm volatile("cp.async.commit_group;" ::: "memory");
    }
    for (int kb = 0; kb < kiters; ++kb) {
        if (kb + 3 < kiters)
            issue1(Ah, lda, Bh, ldb, (kb + 3) * 16, sb + ((kb + 3) & 3) * STAGE1_B, tid);
        asm volatile("cp.async.commit_group;" ::: "memory");
        asm volatile("cp.async.wait_group 3;" ::: "memory");
        __syncthreads();
        compute1(sb + (kb & 3) * STAGE1_B, lane, wm, wn, acc);
        __syncthreads();
    }
}

// Fragment mapping: d0,d1 at (row g, col tq*2..+1); d2,d3 at row g+8.
#define EPILOG_VARS() \
    const int lane = threadIdx.x & 31; \
    const int wid = threadIdx.x >> 5;  \
    const int wm = wid & 1;            \
    const int wn = wid >> 1;           \
    const int g = lane >> 2;           \
    const int tq = lane & 3;

// ---------------------------------------------------------------------------
// Kernel 0a: split weights fp32 -> bf16 hi/lo
// ---------------------------------------------------------------------------
__global__ __launch_bounds__(256) void wsplit_kernel(
    const float* __restrict__ wq, const float* __restrict__ wk,
    const float* __restrict__ wv)
{
    const int idx = blockIdx.x * 256 + threadIdx.x;
    const int which = idx / (CC * CC);
    const int off = idx % (CC * CC);
    const float* src = (which == 0) ? wq : (which == 1) ? wk : wv;
    float v = src[off];
    __nv_bfloat16 h = __float2bfloat16(v);
    g_wh[idx] = h;
    g_wl[idx] = __float2bfloat16(v - __bfloat162float(h));
}

// ---------------------------------------------------------------------------
// Kernel 0b: transpose+split X[B,C,N] -> Xt hi/lo [B,N,C]
// ---------------------------------------------------------------------------
__global__ __launch_bounds__(256) void transpose_kernel(const float* __restrict__ x)
{
    __shared__ float t[32][33];
    const int b = blockIdx.z;
    const int n0 = blockIdx.x * 32;
    const int c0 = blockIdx.y * 32;
    const int tx = threadIdx.x & 31;
    const int ty = threadIdx.x >> 5;
    const float* X = x + (size_t)b * CC * NN;
    __nv_bfloat16* Xh = g_xth + (size_t)b * NN * CC;
    __nv_bfloat16* Xl = g_xtl + (size_t)b * NN * CC;
#pragma unroll
    for (int r = 0; r < 4; ++r)
        t[ty + r * 8][tx] = X[(size_t)(c0 + ty + r * 8) * NN + n0 + tx];
    __syncthreads();
#pragma unroll
    for (int r = 0; r < 4; ++r) {
        float v = t[tx][ty + r * 8];
        __nv_bfloat16 h = __float2bfloat16(v);
        const size_t o = (size_t)(n0 + ty + r * 8) * CC + c0 + tx;
        Xh[o] = h;
        Xl[o] = __float2bfloat16(v - __bfloat162float(h));
    }
}

// ---------------------------------------------------------------------------
// Kernel 1: QKV.  proj 0/1 (3-term): D[n,d]=Xt·W^T+b -> Qt/Kt hi/lo [n,d]
//                 proj 2   (1-term): D[d,n]=Wh·Xh^T+b -> V hi [d,n]
// ---------------------------------------------------------------------------
__global__ __launch_bounds__(256, 2) void qkv_kernel(
    const float* __restrict__ bq, const float* __restrict__ bk,
    const float* __restrict__ bv)
{
    __shared__ __align__(16) char smem[SMEM_TOT];
    const int z = blockIdx.z;
    const int b = z / 3, proj = z % 3;
    const float* bias = (proj == 0) ? bq : (proj == 1) ? bk : bv;
    const __nv_bfloat16* Wh = g_wh + (size_t)proj * CC * CC;
    const __nv_bfloat16* Wl = g_wl + (size_t)proj * CC * CC;
    const __nv_bfloat16* Xh = g_xth + (size_t)b * NN * CC;
    const __nv_bfloat16* Xl = g_xtl + (size_t)b * NN * CC;

    float acc[4][4][4] = {};

    if (proj < 2) {
        const int n0 = blockIdx.x * 128;
        const int d0 = blockIdx.y * 128;
        gemm3(Xh + (size_t)n0 * CC, Xl + (size_t)n0 * CC, CC,
              Wh + (size_t)d0 * CC, Wl + (size_t)d0 * CC, CC,
              CC / 16, smem, acc);
        EPILOG_VARS();
        __nv_bfloat16* dh = ((proj == 0) ? g_qth : g_kth) + (size_t)b * NN * CC;
        __nv_bfloat16* dl = ((proj == 0) ? g_qtl : g_ktl) + (size_t)b * NN * CC;
#pragma unroll
        for (int mt = 0; mt < 4; ++mt) {
            const int n = n0 + wm * 64 + mt * 16 + g;
#pragma unroll
            for (int nt = 0; nt < 4; ++nt) {
                const int d = d0 + wn * 32 + nt * 8 + tq * 2;
                const float2 bb = *(const float2*)(bias + d);
                __nv_bfloat162 h, l;
                split2(acc[mt][nt][0] + bb.x, acc[mt][nt][1] + bb.y, h, l);
                *(__nv_bfloat162*)(dh + (size_t)n * CC + d) = h;
                *(__nv_bfloat162*)(dl + (size_t)n * CC + d) = l;
                split2(acc[mt][nt][2] + bb.x, acc[mt][nt][3] + bb.y, h, l);
                *(__nv_bfloat162*)(dh + (size_t)(n + 8) * CC + d) = h;
                *(__nv_bfloat162*)(dl + (size_t)(n + 8) * CC + d) = l;
            }
        }
    } else {
        const int n0 = blockIdx.x * 128;
        const int d0 = blockIdx.y * 128;
        gemm1(Wh + (size_t)d0 * CC, CC, Xh + (size_t)n0 * CC, CC,
              CC / 16, smem, acc);
        EPILOG_VARS();
        __nv_bfloat16* dh = g_vh + (size_t)b * CC * NN;
#pragma unroll
        for (int mt = 0; mt < 4; ++mt) {
            const int d = d0 + wm * 64 + mt * 16 + g;
            const float b0 = bias[d], b1 = bias[d + 8];
#pragma unroll
            for (int nt = 0; nt < 4; ++nt) {
                const int n = n0 + wn * 32 + nt * 8 + tq * 2;
                *(__nv_bfloat162*)(dh + (size_t)d * NN + n) =
                    __floats2bfloat162_rn(acc[mt][nt][0] + b0, acc[mt][nt][1] + b0);
                *(__nv_bfloat162*)(dh + (size_t)(d + 8) * NN + n) =
                    __floats2bfloat162_rn(acc[mt][nt][2] + b1, acc[mt][nt][3] + b1);
            }
        }
    }
}

// ---------------------------------------------------------------------------
// Kernel 2: energy (3-term). D[i,j] = Qt·Kt^T -> E fp32 [i,j]
// ---------------------------------------------------------------------------
__global__ __launch_bounds__(256, 2) void energy_kernel()
{
    __shared__ __align__(16) char smem[SMEM_TOT];
    const int b = blockIdx.z;
    const int i0 = blockIdx.y * 128;
    const int j0 = blockIdx.x * 128;

    float acc[4][4][4] = {};
    gemm3(g_qth + ((size_t)b * NN + i0) * CC, g_qtl + ((size_t)b * NN + i0) * CC, CC,
          g_kth + ((size_t)b * NN + j0) * CC, g_ktl + ((size_t)b * NN + j0) * CC, CC,
          CC / 16, smem, acc);

    EPILOG_VARS();
    float* E = g_e + (size_t)b * NN * NN;
#pragma unroll
    for (int mt = 0; mt < 4; ++mt) {
        const int i = i0 + wm * 64 + mt * 16 + g;
#pragma unroll
        for (int nt = 0; nt < 4; ++nt) {
            const int j = j0 + wn * 32 + nt * 8 + tq * 2;
            *(float2*)(E + (size_t)i * NN + j) = make_float2(acc[mt][nt][0], acc[mt][nt][1]);
            *(float2*)(E + (size_t)(i + 8) * NN + j) = make_float2(acc[mt][nt][2], acc[mt][nt][3]);
        }
    }
}

// ---------------------------------------------------------------------------
// Kernel 3: row softmax, E fp32 -> P hi bf16
// ---------------------------------------------------------------------------
__global__ __launch_bounds__(256) void softmax_kernel()
{
    const size_t row = blockIdx.x;
    const float* p = g_e + row * (size_t)NN;
    __nv_bfloat162* ph = (__nv_bfloat162*)(g_ph + row * (size_t)NN);
    const int tid = threadIdx.x;

    float4 v[4];
    float mx = -1e30f;
#pragma unroll
    for (int t = 0; t < 4; ++t) {
        v[t] = ((const float4*)p)[tid + t * 256];
        mx = fmaxf(mx, fmaxf(fmaxf(v[t].x, v[t].y), fmaxf(v[t].z, v[t].w)));
    }
    __shared__ float red[8];
#pragma unroll
    for (int o = 16; o > 0; o >>= 1) mx = fmaxf(mx, __shfl_xor_sync(0xffffffffu, mx, o));
    if ((tid & 31) == 0) red[tid >> 5] = mx;
    __syncthreads();
    mx = red[0];
#pragma unroll
    for (int w = 1; w < 8; ++w) mx = fmaxf(mx, red[w]);
    __syncthreads();

    float sum = 0.f;
#pragma unroll
    for (int t = 0; t < 4; ++t) {
        v[t].x = __expf(v[t].x - mx); v[t].y = __expf(v[t].y - mx);
        v[t].z = __expf(v[t].z - mx); v[t].w = __expf(v[t].w - mx);
        sum += v[t].x + v[t].y + v[t].z + v[t].w;
    }
#pragma unroll
    for (int o = 16; o > 0; o >>= 1) sum += __shfl_xor_sync(0xffffffffu, sum, o);
    if ((tid & 31) == 0) red[tid >> 5] = sum;
    __syncthreads();
    sum = 0.f;
#pragma unroll
    for (int w = 0; w < 8; ++w) sum += red[w];

    const float inv = 1.0f / sum;
#pragma unroll
    for (int t = 0; t < 4; ++t) {
        const int o2 = (tid + t * 256) * 2;
        ph[o2]     = __floats2bfloat162_rn(v[t].x * inv, v[t].y * inv);
        ph[o2 + 1] = __floats2bfloat162_rn(v[t].z * inv, v[t].w * inv);
    }
}

// ---------------------------------------------------------------------------
// Kernel 4: VA + residual (1-term). D[c,i] = Vh·Ph^T -> out[c,i]
// ---------------------------------------------------------------------------
__global__ __launch_bounds__(256, 2) void va_kernel(
    const float* __restrict__ pose, const float* __restrict__ gamma,
    float* __restrict__ out)
{
    __shared__ __align__(16) char smem[SMEM_TOT];
    const int b = blockIdx.z;
    const int c0 = blockIdx.y * 128;
    const int i0 = blockIdx.x * 128;

    float acc[4][4][4] = {};
    gemm1(g_vh + ((size_t)b * CC + c0) * NN, NN,
          g_ph + ((size_t)b * NN + i0) * NN, NN,
          NN / 16, smem, acc);

    EPILOG_VARS();
    const float gm = gamma[0];
#pragma unroll
    for (int mt = 0; mt < 4; ++mt) {
        const int c = c0 + wm * 64 + mt * 16 + g;
#pragma unroll
        for (int nt = 0; nt < 4; ++nt) {
            const int i = i0 + wn * 32 + nt * 8 + tq * 2;
            const size_t i1 = ((size_t)b * CC + c) * NN + i;
            const size_t i2 = ((size_t)b * CC + c + 8) * NN + i;
            float2 p1 = *(const float2*)(pose + i1);
            float2 p2 = *(const float2*)(pose + i2);
            *(float2*)(out + i1) = make_float2(fmaf(gm, acc[mt][nt][0], p1.x),
                                               fmaf(gm, acc[mt][nt][1], p1.y));
            *(float2*)(out + i2) = make_float2(fmaf(gm, acc[mt][nt][2], p2.x),
                                               fmaf(gm, acc[mt][nt][3], p2.y));
        }
    }
}

// ---------------------------------------------------------------------------
extern "C" void kernel_launch(void* const* d_in, const int* in_sizes, int n_in,
                              void* d_out, int out_size)
{
    const float* pose  = (const float*)d_in[0];
    const float* wq    = (const float*)d_in[1];
    const float* bq    = (const float*)d_in[2];
    const float* wk    = (const float*)d_in[3];
    const float* bk    = (const float*)d_in[4];
    const float* wv    = (const float*)d_in[5];
    const float* bv    = (const float*)d_in[6];
    const float* gamma = (const float*)d_in[7];
    float* out = (float*)d_out;

    wsplit_kernel   <<<3 * CC * CC / 256, 256>>>(wq, wk, wv);
    transpose_kernel<<<dim3(NN / 32, CC / 32, BB), 256>>>(pose);
    qkv_kernel      <<<dim3(NN / 128, CC / 128, 3 * BB), 256>>>(bq, bk, bv);
    energy_kernel   <<<dim3(NN / 128, NN / 128, BB), 256>>>();
    softmax_kernel  <<<dim3(BB * NN), 256>>>();
    va_kernel       <<<dim3(NN / 128, CC / 128, BB), 256>>>(pose, gamma, out);
}

// round 12
// speedup vs baseline: 3.5453x; 1.0159x over previous
#include <cuda_runtime.h>
#include <cuda_bf16.h>
#include <cstdint>

#define BB 4
#define CC 256
#define NN 4096

// ---------------- scratch (__device__ globals; allocation-free rule) -------
__device__ __nv_bfloat16 g_xth[BB * NN * CC], g_xtl[BB * NN * CC];   // Xt [B,N,C]
__device__ __nv_bfloat16 g_qth[BB * NN * CC], g_qtl[BB * NN * CC];   // Qt [B,N,C]
__device__ __nv_bfloat16 g_kth[BB * NN * CC], g_ktl[BB * NN * CC];   // Kt [B,N,C]
__device__ __nv_bfloat16 g_vh [BB * CC * NN];                        // V  [B,C,N] (hi only)
__device__ __nv_bfloat16 g_wh [3 * CC * CC],  g_wl [3 * CC * CC];    // W split
__device__ float         g_e  [(size_t)BB * NN * NN];                // E fp32
__device__ __nv_bfloat16 g_ph [(size_t)BB * NN * NN];                // P hi only

// Tile = 128 rows x 16 bf16 = 32B/row = 2x16B chunks; swizzle chunk^=(row>>2)&1.
#define TILE_B    4096
#define STAGE3_B  (4 * TILE_B)   // Ahi, Alo, Bhi, Blo  (3-term path), 2 stages
#define STAGE1_B  (2 * TILE_B)   // Ah, Bh              (1-term path), 4 stages
#define SMEM_TOT  32768          // 2 x STAGE3_B == 4 x STAGE1_B  (R8-proven)

static __device__ __forceinline__ uint32_t smem_u32(const void* p) {
    uint32_t a;
    asm("{ .reg .u64 t; cvta.to.shared.u64 t, %1; cvt.u32.u64 %0, t; }" : "=r"(a) : "l"(p));
    return a;
}
static __device__ __forceinline__ void cp16(uint32_t dst, const void* src) {
    asm volatile("cp.async.cg.shared.global [%0], [%1], 16;" :: "r"(dst), "l"(src));
}
static __device__ __forceinline__ void ldmx4(uint32_t& r0, uint32_t& r1, uint32_t& r2,
                                             uint32_t& r3, uint32_t addr) {
    asm volatile("ldmatrix.sync.aligned.m8n8.x4.shared.b16 {%0,%1,%2,%3}, [%4];"
                 : "=r"(r0), "=r"(r1), "=r"(r2), "=r"(r3) : "r"(addr));
}
static __device__ __forceinline__ void ldmx2(uint32_t& r0, uint32_t& r1, uint32_t addr) {
    asm volatile("ldmatrix.sync.aligned.m8n8.x2.shared.b16 {%0,%1}, [%2];"
                 : "=r"(r0), "=r"(r1) : "r"(addr));
}
static __device__ __forceinline__ void mma16816(float* d, uint32_t a0, uint32_t a1,
                                                uint32_t a2, uint32_t a3,
                                                uint32_t b0, uint32_t b1) {
    asm volatile(
        "mma.sync.aligned.m16n8k16.row.col.f32.bf16.bf16.f32 "
        "{%0,%1,%2,%3}, {%4,%5,%6,%7}, {%8,%9}, {%0,%1,%2,%3};"
        : "+f"(d[0]), "+f"(d[1]), "+f"(d[2]), "+f"(d[3])
        : "r"(a0), "r"(a1), "r"(a2), "r"(a3), "r"(b0), "r"(b1));
}
static __device__ __forceinline__ void split2(float x, float y,
                                              __nv_bfloat162& h, __nv_bfloat162& l) {
    h = __floats2bfloat162_rn(x, y);
    float2 f = __bfloat1622float2(h);
    l = __floats2bfloat162_rn(x - f.x, y - f.y);
}

// ---------------------- 3-term pipeline (2 stages, R8-proven) --------------
static __device__ __forceinline__ void issue3(
    const __nv_bfloat16* __restrict__ Ahi, const __nv_bfloat16* __restrict__ Alo, int lda,
    const __nv_bfloat16* __restrict__ Bhi, const __nv_bfloat16* __restrict__ Blo, int ldb,
    int k0, uint32_t st, int tid)
{
    const int row = tid >> 1;
    const int chunk = tid & 1;
    const uint32_t dsto = row * 32 + ((chunk ^ ((row >> 2) & 1)) * 16);
    const size_t asrc = (size_t)row * lda + k0 + chunk * 8;
    const size_t bsrc = (size_t)row * ldb + k0 + chunk * 8;
    cp16(st + dsto,              Ahi + asrc);
    cp16(st + TILE_B + dsto,     Alo + asrc);
    cp16(st + 2 * TILE_B + dsto, Bhi + bsrc);
    cp16(st + 3 * TILE_B + dsto, Blo + bsrc);
}

static __device__ __forceinline__ void compute3(
    uint32_t st, int lane, int wm, int wn, float acc[4][4][4])
{
    const uint32_t rowA = wm * 64 + (lane & 15);
    const uint32_t rowB = wn * 32 + (lane & 7);
    const uint32_t cA = ((lane >> 4) & 1) ^ (((lane & 15) >> 2) & 1);
    const uint32_t cB = ((lane >> 3) & 1) ^ (((lane & 7) >> 2) & 1);

    uint32_t bh[4][2], bl[4][2];
#pragma unroll
    for (int nt = 0; nt < 4; ++nt) {
        const uint32_t bo = (rowB + nt * 8) * 32 + cB * 16;
        ldmx2(bh[nt][0], bh[nt][1], st + 2 * TILE_B + bo);
        ldmx2(bl[nt][0], bl[nt][1], st + 3 * TILE_B + bo);
    }
#pragma unroll
    for (int mt = 0; mt < 4; ++mt) {
        const uint32_t ao = (rowA + mt * 16) * 32 + cA * 16;
        uint32_t ah0, ah1, ah2, ah3, al0, al1, al2, al3;
        ldmx4(ah0, ah1, ah2, ah3, st + ao);
        ldmx4(al0, al1, al2, al3, st + TILE_B + ao);
#pragma unroll
        for (int nt = 0; nt < 4; ++nt) {
            mma16816(acc[mt][nt], ah0, ah1, ah2, ah3, bh[nt][0], bh[nt][1]);
            mma16816(acc[mt][nt], ah0, ah1, ah2, ah3, bl[nt][0], bl[nt][1]);
            mma16816(acc[mt][nt], al0, al1, al2, al3, bh[nt][0], bh[nt][1]);
        }
    }
}

static __device__ __forceinline__ void gemm3(
    const __nv_bfloat16* __restrict__ Ahi, const __nv_bfloat16* __restrict__ Alo, int lda,
    const __nv_bfloat16* __restrict__ Bhi, const __nv_bfloat16* __restrict__ Blo, int ldb,
    int kiters, char* smem, float acc[4][4][4])
{
    const int tid = threadIdx.x;
    const int lane = tid & 31, wid = tid >> 5;
    const int wm = wid & 1, wn = wid >> 1;
    const uint32_t sb = smem_u32(smem);

    issue3(Ahi, Alo, lda, Bhi, Blo, ldb, 0, sb, tid);
    asm volatile("cp.async.commit_group;" ::: "memory");
    for (int kb = 0; kb < kiters; ++kb) {
        if (kb + 1 < kiters)
            issue3(Ahi, Alo, lda, Bhi, Blo, ldb, (kb + 1) * 16,
                   sb + ((kb + 1) & 1) * STAGE3_B, tid);
        asm volatile("cp.async.commit_group;" ::: "memory");
        asm volatile("cp.async.wait_group 1;" ::: "memory");
        __syncthreads();
        compute3(sb + (kb & 1) * STAGE3_B, lane, wm, wn, acc);
        __syncthreads();
    }
}

// ------------- 1-term pipeline (4 stages, SINGLE barrier per stage) --------
static __device__ __forceinline__ void issue1(
    const __nv_bfloat16* __restrict__ Ah, int lda,
    const __nv_bfloat16* __restrict__ Bh, int ldb,
    int k0, uint32_t st, int tid)
{
    const int row = tid >> 1;
    const int chunk = tid & 1;
    const uint32_t dsto = row * 32 + ((chunk ^ ((row >> 2) & 1)) * 16);
    cp16(st + dsto,          Ah + (size_t)row * lda + k0 + chunk * 8);
    cp16(st + TILE_B + dsto, Bh + (size_t)row * ldb + k0 + chunk * 8);
}

static __device__ __forceinline__ void compute1(
    uint32_t st, int lane, int wm, int wn, float acc[4][4][4])
{
    const uint32_t rowA = wm * 64 + (lane & 15);
    const uint32_t rowB = wn * 32 + (lane & 7);
    const uint32_t cA = ((lane >> 4) & 1) ^ (((lane & 15) >> 2) & 1);
    const uint32_t cB = ((lane >> 3) & 1) ^ (((lane & 7) >> 2) & 1);

    uint32_t bh[4][2];
#pragma unroll
    for (int nt = 0; nt < 4; ++nt) {
        const uint32_t bo = (rowB + nt * 8) * 32 + cB * 16;
        ldmx2(bh[nt][0], bh[nt][1], st + TILE_B + bo);
    }
#pragma unroll
    for (int mt = 0; mt < 4; ++mt) {
        const uint32_t ao = (rowA + mt * 16) * 32 + cA * 16;
        uint32_t a0, a1, a2, a3;
        ldmx4(a0, a1, a2, a3, st + ao);
#pragma unroll
        for (int nt = 0; nt < 4; ++nt)
            mma16816(acc[mt][nt], a0, a1, a2, a3, bh[nt][0], bh[nt][1]);
    }
}

static __device__ __forceinline__ void gemm1(
    const __nv_bfloat16* __restrict__ Ah, int lda,
    const __nv_bfloat16* __restrict__ Bh, int ldb,
    int kiters, char* smem, float acc[4][4][4])
{
    const int tid = threadIdx.x;
    const int lane = tid & 31, wid = tid >> 5;
    const int wm = wid & 1, wn = wid >> 1;
    const uint32_t sb = smem_u32(smem);

#pragma unroll
    for (int s = 0; s < 3; ++s) {
        issue1(Ah, lda, Bh, ldb, s * 16, sb + s * STAGE1_B, tid);
        asm volatile("cp.async.commit_group;" ::: "memory");
    }
    // wait(kb) -> barrier -> issue(kb+3) -> commit -> compute(kb).
    // Barrier proves compute(kb-1) retired in all warps, so refilling buffer
    // (kb+3)&3 == (kb-1)&3 after it is WAR-safe; wait before the barrier
    // makes every thread's stage-kb data visible to all consumers.
    for (int kb = 0; kb < kiters; ++kb) {
        asm volatile("cp.async.wait_group 2;" ::: "memory");
        __syncthreads();
        if (kb + 3 < kiters)
            issue1(Ah, lda, Bh, ldb, (kb + 3) * 16, sb + ((kb + 3) & 3) * STAGE1_B, tid);
        asm volatile("cp.async.commit_group;" ::: "memory");
        compute1(sb + (kb & 3) * STAGE1_B, lane, wm, wn, acc);
    }
}

// Fragment mapping: d0,d1 at (row g, col tq*2..+1); d2,d3 at row g+8.
#define EPILOG_VARS() \
    const int lane = threadIdx.x & 31; \
    const int wid = threadIdx.x >> 5;  \
    const int wm = wid & 1;            \
    const int wn = wid >> 1;           \
    const int g = lane >> 2;           \
    const int tq = lane & 3;

// ---------------------------------------------------------------------------
// Kernel 0a: split weights fp32 -> bf16 hi/lo
// ---------------------------------------------------------------------------
__global__ __launch_bounds__(256) void wsplit_kernel(
    const float* __restrict__ wq, const float* __restrict__ wk,
    const float* __restrict__ wv)
{
    const int idx = blockIdx.x * 256 + threadIdx.x;
    const int which = idx / (CC * CC);
    const int off = idx % (CC * CC);
    const float* src = (which == 0) ? wq : (which == 1) ? wk : wv;
    float v = src[off];
    __nv_bfloat16 h = __float2bfloat16(v);
    g_wh[idx] = h;
    g_wl[idx] = __float2bfloat16(v - __bfloat162float(h));
}

// ---------------------------------------------------------------------------
// Kernel 0b: transpose+split X[B,C,N] -> Xt hi/lo [B,N,C]
// ---------------------------------------------------------------------------
__global__ __launch_bounds__(256) void transpose_kernel(const float* __restrict__ x)
{
    __shared__ float t[32][33];
    const int b = blockIdx.z;
    const int n0 = blockIdx.x * 32;
    const int c0 = blockIdx.y * 32;
    const int tx = threadIdx.x & 31;
    const int ty = threadIdx.x >> 5;
    const float* X = x + (size_t)b * CC * NN;
    __nv_bfloat16* Xh = g_xth + (size_t)b * NN * CC;
    __nv_bfloat16* Xl = g_xtl + (size_t)b * NN * CC;
#pragma unroll
    for (int r = 0; r < 4; ++r)
        t[ty + r * 8][tx] = X[(size_t)(c0 + ty + r * 8) * NN + n0 + tx];
    __syncthreads();
#pragma unroll
    for (int r = 0; r < 4; ++r) {
        float v = t[tx][ty + r * 8];
        __nv_bfloat16 h = __float2bfloat16(v);
        const size_t o = (size_t)(n0 + ty + r * 8) * CC + c0 + tx;
        Xh[o] = h;
        Xl[o] = __float2bfloat16(v - __bfloat162float(h));
    }
}

// ---------------------------------------------------------------------------
// Kernel 1: QKV.  proj 0/1 (3-term): D[n,d]=Xt·W^T+b -> Qt/Kt hi/lo [n,d]
//                 proj 2   (1-term): D[d,n]=Wh·Xh^T+b -> V hi [d,n]
// ---------------------------------------------------------------------------
__global__ __launch_bounds__(256, 2) void qkv_kernel(
    const float* __restrict__ bq, const float* __restrict__ bk,
    const float* __restrict__ bv)
{
    __shared__ __align__(16) char smem[SMEM_TOT];
    const int z = blockIdx.z;
    const int b = z / 3, proj = z % 3;
    const float* bias = (proj == 0) ? bq : (proj == 1) ? bk : bv;
    const __nv_bfloat16* Wh = g_wh + (size_t)proj * CC * CC;
    const __nv_bfloat16* Wl = g_wl + (size_t)proj * CC * CC;
    const __nv_bfloat16* Xh = g_xth + (size_t)b * NN * CC;
    const __nv_bfloat16* Xl = g_xtl + (size_t)b * NN * CC;

    float acc[4][4][4] = {};

    if (proj < 2) {
        const int n0 = blockIdx.x * 128;
        const int d0 = blockIdx.y * 128;
        gemm3(Xh + (size_t)n0 * CC, Xl + (size_t)n0 * CC, CC,
              Wh + (size_t)d0 * CC, Wl + (size_t)d0 * CC, CC,
              CC / 16, smem, acc);
        EPILOG_VARS();
        __nv_bfloat16* dh = ((proj == 0) ? g_qth : g_kth) + (size_t)b * NN * CC;
        __nv_bfloat16* dl = ((proj == 0) ? g_qtl : g_ktl) + (size_t)b * NN * CC;
#pragma unroll
        for (int mt = 0; mt < 4; ++mt) {
            const int n = n0 + wm * 64 + mt * 16 + g;
#pragma unroll
            for (int nt = 0; nt < 4; ++nt) {
                const int d = d0 + wn * 32 + nt * 8 + tq * 2;
                const float2 bb = *(const float2*)(bias + d);
                __nv_bfloat162 h, l;
                split2(acc[mt][nt][0] + bb.x, acc[mt][nt][1] + bb.y, h, l);
                *(__nv_bfloat162*)(dh + (size_t)n * CC + d) = h;
                *(__nv_bfloat162*)(dl + (size_t)n * CC + d) = l;
                split2(acc[mt][nt][2] + bb.x, acc[mt][nt][3] + bb.y, h, l);
                *(__nv_bfloat162*)(dh + (size_t)(n + 8) * CC + d) = h;
                *(__nv_bfloat162*)(dl + (size_t)(n + 8) * CC + d) = l;
            }
        }
    } else {
        const int n0 = blockIdx.x * 128;
        const int d0 = blockIdx.y * 128;
        gemm1(Wh + (size_t)d0 * CC, CC, Xh + (size_t)n0 * CC, CC,
              CC / 16, smem, acc);
        EPILOG_VARS();
        __nv_bfloat16* dh = g_vh + (size_t)b * CC * NN;
#pragma unroll
        for (int mt = 0; mt < 4; ++mt) {
            const int d = d0 + wm * 64 + mt * 16 + g;
            const float b0 = bias[d], b1 = bias[d + 8];
#pragma unroll
            for (int nt = 0; nt < 4; ++nt) {
                const int n = n0 + wn * 32 + nt * 8 + tq * 2;
                *(__nv_bfloat162*)(dh + (size_t)d * NN + n) =
                    __floats2bfloat162_rn(acc[mt][nt][0] + b0, acc[mt][nt][1] + b0);
                *(__nv_bfloat162*)(dh + (size_t)(d + 8) * NN + n) =
                    __floats2bfloat162_rn(acc[mt][nt][2] + b1, acc[mt][nt][3] + b1);
            }
        }
    }
}

// ---------------------------------------------------------------------------
// Kernel 2: energy (3-term). D[i,j] = Qt·Kt^T -> E fp32 [i,j]
// ---------------------------------------------------------------------------
__global__ __launch_bounds__(256, 2) void energy_kernel()
{
    __shared__ __align__(16) char smem[SMEM_TOT];
    const int b = blockIdx.z;
    const int i0 = blockIdx.y * 128;
    const int j0 = blockIdx.x * 128;

    float acc[4][4][4] = {};
    gemm3(g_qth + ((size_t)b * NN + i0) * CC, g_qtl + ((size_t)b * NN + i0) * CC, CC,
          g_kth + ((size_t)b * NN + j0) * CC, g_ktl + ((size_t)b * NN + j0) * CC, CC,
          CC / 16, smem, acc);

    EPILOG_VARS();
    float* E = g_e + (size_t)b * NN * NN;
#pragma unroll
    for (int mt = 0; mt < 4; ++mt) {
        const int i = i0 + wm * 64 + mt * 16 + g;
#pragma unroll
        for (int nt = 0; nt < 4; ++nt) {
            const int j = j0 + wn * 32 + nt * 8 + tq * 2;
            *(float2*)(E + (size_t)i * NN + j) = make_float2(acc[mt][nt][0], acc[mt][nt][1]);
            *(float2*)(E + (size_t)(i + 8) * NN + j) = make_float2(acc[mt][nt][2], acc[mt][nt][3]);
        }
    }
}

// ---------------------------------------------------------------------------
// Kernel 3: row softmax, E fp32 -> P hi bf16
// ---------------------------------------------------------------------------
__global__ __launch_bounds__(256) void softmax_kernel()
{
    const size_t row = blockIdx.x;
    const float* p = g_e + row * (size_t)NN;
    __nv_bfloat162* ph = (__nv_bfloat162*)(g_ph + row * (size_t)NN);
    const int tid = threadIdx.x;

    float4 v[4];
    float mx = -1e30f;
#pragma unroll
    for (int t = 0; t < 4; ++t) {
        v[t] = ((const float4*)p)[tid + t * 256];
        mx = fmaxf(mx, fmaxf(fmaxf(v[t].x, v[t].y), fmaxf(v[t].z, v[t].w)));
    }
    __shared__ float red[8];
#pragma unroll
    for (int o = 16; o > 0; o >>= 1) mx = fmaxf(mx, __shfl_xor_sync(0xffffffffu, mx, o));
    if ((tid & 31) == 0) red[tid >> 5] = mx;
    __syncthreads();
    mx = red[0];
#pragma unroll
    for (int w = 1; w < 8; ++w) mx = fmaxf(mx, red[w]);
    __syncthreads();

    float sum = 0.f;
#pragma unroll
    for (int t = 0; t < 4; ++t) {
        v[t].x = __expf(v[t].x - mx); v[t].y = __expf(v[t].y - mx);
        v[t].z = __expf(v[t].z - mx); v[t].w = __expf(v[t].w - mx);
        sum += v[t].x + v[t].y + v[t].z + v[t].w;
    }
#pragma unroll
    for (int o = 16; o > 0; o >>= 1) sum += __shfl_xor_sync(0xffffffffu, sum, o);
    if ((tid & 31) == 0) red[tid >> 5] = sum;
    __syncthreads();
    sum = 0.f;
#pragma unroll
    for (int w = 0; w < 8; ++w) sum += red[w];

    const float inv = 1.0f / sum;
#pragma unroll
    for (int t = 0; t < 4; ++t) {
        const int o2 = (tid + t * 256) * 2;
        ph[o2]     = __floats2bfloat162_rn(v[t].x * inv, v[t].y * inv);
        ph[o2 + 1] = __floats2bfloat162_rn(v[t].z * inv, v[t].w * inv);
    }
}

// ---------------------------------------------------------------------------
// Kernel 4: VA + residual (1-term). D[c,i] = Vh·Ph^T -> out[c,i]
// ---------------------------------------------------------------------------
__global__ __launch_bounds__(256, 2) void va_kernel(
    const float* __restrict__ pose, const float* __restrict__ gamma,
    float* __restrict__ out)
{
    __shared__ __align__(16) char smem[SMEM_TOT];
    const int b = blockIdx.z;
    const int c0 = blockIdx.y * 128;
    const int i0 = blockIdx.x * 128;

    float acc[4][4][4] = {};
    gemm1(g_vh + ((size_t)b * CC + c0) * NN, NN,
          g_ph + ((size_t)b * NN + i0) * NN, NN,
          NN / 16, smem, acc);

    EPILOG_VARS();
    const float gm = gamma[0];
#pragma unroll
    for (int mt = 0; mt < 4; ++mt) {
        const int c = c0 + wm * 64 + mt * 16 + g;
#pragma unroll
        for (int nt = 0; nt < 4; ++nt) {
            const int i = i0 + wn * 32 + nt * 8 + tq * 2;
            const size_t i1 = ((size_t)b * CC + c) * NN + i;
            const size_t i2 = ((size_t)b * CC + c + 8) * NN + i;
            float2 p1 = *(const float2*)(pose + i1);
            float2 p2 = *(const float2*)(pose + i2);
            *(float2*)(out + i1) = make_float2(fmaf(gm, acc[mt][nt][0], p1.x),
                                               fmaf(gm, acc[mt][nt][1], p1.y));
            *(float2*)(out + i2) = make_float2(fmaf(gm, acc[mt][nt][2], p2.x),
                                               fmaf(gm, acc[mt][nt][3], p2.y));
        }
    }
}

// ---------------------------------------------------------------------------
extern "C" void kernel_launch(void* const* d_in, const int* in_sizes, int n_in,
                              void* d_out, int out_size)
{
    const float* pose  = (const float*)d_in[0];
    const float* wq    = (const float*)d_in[1];
    const float* bq    = (const float*)d_in[2];
    const float* wk    = (const float*)d_in[3];
    const float* bk    = (const float*)d_in[4];
    const float* wv    = (const float*)d_in[5];
    const float* bv    = (const float*)d_in[6];
    const float* gamma = (const float*)d_in[7];
    float* out = (float*)d_out;

    wsplit_kernel   <<<3 * CC * CC / 256, 256>>>(wq, wk, wv);
    transpose_kernel<<<dim3(NN / 32, CC / 32, BB), 256>>>(pose);
    qkv_kernel      <<<dim3(NN / 128, CC / 128, 3 * BB), 256>>>(bq, bk, bv);
    energy_kernel   <<<dim3(NN / 128, NN / 128, BB), 256>>>();
    softmax_kernel  <<<dim3(BB * NN), 256>>>();
    va_kernel       <<<dim3(NN / 128, CC / 128, BB), 256>>>(pose, gamma, out);
}

// round 13
// speedup vs baseline: 3.9638x; 1.1180x over previous
#include <cuda_runtime.h>
#include <cuda_bf16.h>
#include <cstdint>

#define BB 4
#define CC 256
#define NN 4096

// ---------------- scratch (__device__ globals; allocation-free rule) -------
__device__ __nv_bfloat16 g_xth[BB * NN * CC], g_xtl[BB * NN * CC];   // Xt [B,N,C]
__device__ __nv_bfloat16 g_qth[BB * NN * CC], g_qtl[BB * NN * CC];   // Qt [B,N,C]
__device__ __nv_bfloat16 g_kth[BB * NN * CC], g_ktl[BB * NN * CC];   // Kt [B,N,C]
__device__ __nv_bfloat16 g_vh [BB * CC * NN];                        // V  [B,C,N] (hi only)
__device__ __nv_bfloat16 g_wh [3 * CC * CC],  g_wl [3 * CC * CC];    // W split
__device__ float         g_e  [(size_t)BB * NN * NN];                // E fp32
__device__ __nv_bfloat16 g_ph [(size_t)BB * NN * NN];                // P hi only

// Tile = 128 rows x 16 bf16 = 32B/row = 2x16B chunks; swizzle chunk^=(row>>2)&1.
#define TILE_B    4096
#define STAGE3_B  (4 * TILE_B)   // Ahi, Alo, Bhi, Blo  (3-term path), 2 stages
#define STAGE1_B  (2 * TILE_B)   // Ah, Bh              (1-term path), 4 stages
#define SMEM_TOT  32768          // 2 x STAGE3_B == 4 x STAGE1_B  (proven)

static __device__ __forceinline__ uint32_t smem_u32(const void* p) {
    uint32_t a;
    asm("{ .reg .u64 t; cvta.to.shared.u64 t, %1; cvt.u32.u64 %0, t; }" : "=r"(a) : "l"(p));
    return a;
}
static __device__ __forceinline__ void cp16(uint32_t dst, const void* src) {
    asm volatile("cp.async.cg.shared.global [%0], [%1], 16;" :: "r"(dst), "l"(src));
}
static __device__ __forceinline__ void ldmx4(uint32_t& r0, uint32_t& r1, uint32_t& r2,
                                             uint32_t& r3, uint32_t addr) {
    asm volatile("ldmatrix.sync.aligned.m8n8.x4.shared.b16 {%0,%1,%2,%3}, [%4];"
                 : "=r"(r0), "=r"(r1), "=r"(r2), "=r"(r3) : "r"(addr));
}
static __device__ __forceinline__ void mma16816(float* d, uint32_t a0, uint32_t a1,
                                                uint32_t a2, uint32_t a3,
                                                uint32_t b0, uint32_t b1) {
    asm volatile(
        "mma.sync.aligned.m16n8k16.row.col.f32.bf16.bf16.f32 "
        "{%0,%1,%2,%3}, {%4,%5,%6,%7}, {%8,%9}, {%0,%1,%2,%3};"
        : "+f"(d[0]), "+f"(d[1]), "+f"(d[2]), "+f"(d[3])
        : "r"(a0), "r"(a1), "r"(a2), "r"(a3), "r"(b0), "r"(b1));
}
static __device__ __forceinline__ void split2(float x, float y,
                                              __nv_bfloat162& h, __nv_bfloat162& l) {
    h = __floats2bfloat162_rn(x, y);
    float2 f = __bfloat1622float2(h);
    l = __floats2bfloat162_rn(x - f.x, y - f.y);
}

// B-fragment loader: one ldmx4 covers an nt-pair (rows +0/+8) x both k-halves.
// row = base + p*16 + ((lane>>4)&1)*8 + (lane&7); khalf = (lane>>3)&1.
// Swizzle keys off row-bit-2 (= lane-bit-2 only; +8/+16/+32 offsets don't touch it).
#define B_PAIR_OFF(base_row, lane, p) \
    ((((base_row) + (p) * 16 + (((lane) >> 4) & 1) * 8 + ((lane) & 7)) * 32) + \
     (((((lane) >> 3) & 1) ^ ((((lane) & 7) >> 2) & 1)) * 16))

// ---------------------- 3-term pipeline (2 stages, 1 barrier/stage) --------
static __device__ __forceinline__ void issue3(
    const __nv_bfloat16* __restrict__ Ahi, const __nv_bfloat16* __restrict__ Alo, int lda,
    const __nv_bfloat16* __restrict__ Bhi, const __nv_bfloat16* __restrict__ Blo, int ldb,
    int k0, uint32_t st, int tid)
{
    const int row = tid >> 1;
    const int chunk = tid & 1;
    const uint32_t dsto = row * 32 + ((chunk ^ ((row >> 2) & 1)) * 16);
    const size_t asrc = (size_t)row * lda + k0 + chunk * 8;
    const size_t bsrc = (size_t)row * ldb + k0 + chunk * 8;
    cp16(st + dsto,              Ahi + asrc);
    cp16(st + TILE_B + dsto,     Alo + asrc);
    cp16(st + 2 * TILE_B + dsto, Bhi + bsrc);
    cp16(st + 3 * TILE_B + dsto, Blo + bsrc);
}

static __device__ __forceinline__ void compute3(
    uint32_t st, int lane, int wm, int wn, float acc[4][4][4])
{
    const uint32_t rowA = wm * 64 + (lane & 15);
    const uint32_t cA = ((lane >> 4) & 1) ^ (((lane & 15) >> 2) & 1);

    uint32_t bh[4][2], bl[4][2];
#pragma unroll
    for (int p = 0; p < 2; ++p) {
        const uint32_t bo = B_PAIR_OFF(wn * 32, lane, p);
        ldmx4(bh[2 * p][0], bh[2 * p][1], bh[2 * p + 1][0], bh[2 * p + 1][1],
              st + 2 * TILE_B + bo);
        ldmx4(bl[2 * p][0], bl[2 * p][1], bl[2 * p + 1][0], bl[2 * p + 1][1],
              st + 3 * TILE_B + bo);
    }
#pragma unroll
    for (int mt = 0; mt < 4; ++mt) {
        const uint32_t ao = (rowA + mt * 16) * 32 + cA * 16;
        uint32_t ah0, ah1, ah2, ah3, al0, al1, al2, al3;
        ldmx4(ah0, ah1, ah2, ah3, st + ao);
        ldmx4(al0, al1, al2, al3, st + TILE_B + ao);
#pragma unroll
        for (int nt = 0; nt < 4; ++nt) {
            mma16816(acc[mt][nt], ah0, ah1, ah2, ah3, bh[nt][0], bh[nt][1]);
            mma16816(acc[mt][nt], ah0, ah1, ah2, ah3, bl[nt][0], bl[nt][1]);
            mma16816(acc[mt][nt], al0, al1, al2, al3, bh[nt][0], bh[nt][1]);
        }
    }
}

static __device__ __forceinline__ void gemm3(
    const __nv_bfloat16* __restrict__ Ahi, const __nv_bfloat16* __restrict__ Alo, int lda,
    const __nv_bfloat16* __restrict__ Bhi, const __nv_bfloat16* __restrict__ Blo, int ldb,
    int kiters, char* smem, float acc[4][4][4])
{
    const int tid = threadIdx.x;
    const int lane = tid & 31, wid = tid >> 5;
    const int wm = wid & 1, wn = wid >> 1;
    const uint32_t sb = smem_u32(smem);

    issue3(Ahi, Alo, lda, Bhi, Blo, ldb, 0, sb, tid);
    asm volatile("cp.async.commit_group;" ::: "memory");
    // wait(kb) -> barrier -> issue(kb+1) -> commit -> compute(kb).
    // Barrier proves compute(kb-1) retired in all warps, so refilling buffer
    // (kb+1)&1 == (kb-1)&1 after it is WAR-safe; the load of kb+1 overlaps
    // compute(kb). One barrier per stage (same proven schedule as gemm1).
    for (int kb = 0; kb < kiters; ++kb) {
        asm volatile("cp.async.wait_group 0;" ::: "memory");
        __syncthreads();
        if (kb + 1 < kiters)
            issue3(Ahi, Alo, lda, Bhi, Blo, ldb, (kb + 1) * 16,
                   sb + ((kb + 1) & 1) * STAGE3_B, tid);
        asm volatile("cp.async.commit_group;" ::: "memory");
        compute3(sb + (kb & 1) * STAGE3_B, lane, wm, wn, acc);
    }
}

// ------------- 1-term pipeline (4 stages, 1 barrier/stage, R12-proven) -----
static __device__ __forceinline__ void issue1(
    const __nv_bfloat16* __restrict__ Ah, int lda,
    const __nv_bfloat16* __restrict__ Bh, int ldb,
    int k0, uint32_t st, int tid)
{
    const int row = tid >> 1;
    const int chunk = tid & 1;
    const uint32_t dsto = row * 32 + ((chunk ^ ((row >> 2) & 1)) * 16);
    cp16(st + dsto,          Ah + (size_t)row * lda + k0 + chunk * 8);
    cp16(st + TILE_B + dsto, Bh + (size_t)row * ldb + k0 + chunk * 8);
}

static __device__ __forceinline__ void compute1(
    uint32_t st, int lane, int wm, int wn, float acc[4][4][4])
{
    const uint32_t rowA = wm * 64 + (lane & 15);
    const uint32_t cA = ((lane >> 4) & 1) ^ (((lane & 15) >> 2) & 1);

    uint32_t bh[4][2];
#pragma unroll
    for (int p = 0; p < 2; ++p) {
        const uint32_t bo = B_PAIR_OFF(wn * 32, lane, p);
        ldmx4(bh[2 * p][0], bh[2 * p][1], bh[2 * p + 1][0], bh[2 * p + 1][1],
              st + TILE_B + bo);
    }
#pragma unroll
    for (int mt = 0; mt < 4; ++mt) {
        const uint32_t ao = (rowA + mt * 16) * 32 + cA * 16;
        uint32_t a0, a1, a2, a3;
        ldmx4(a0, a1, a2, a3, st + ao);
#pragma unroll
        for (int nt = 0; nt < 4; ++nt)
            mma16816(acc[mt][nt], a0, a1, a2, a3, bh[nt][0], bh[nt][1]);
    }
}

static __device__ __forceinline__ void gemm1(
    const __nv_bfloat16* __restrict__ Ah, int lda,
    const __nv_bfloat16* __restrict__ Bh, int ldb,
    int kiters, char* smem, float acc[4][4][4])
{
    const int tid = threadIdx.x;
    const int lane = tid & 31, wid = tid >> 5;
    const int wm = wid & 1, wn = wid >> 1;
    const uint32_t sb = smem_u32(smem);

#pragma unroll
    for (int s = 0; s < 3; ++s) {
        issue1(Ah, lda, Bh, ldb, s * 16, sb + s * STAGE1_B, tid);
        asm volatile("cp.async.commit_group;" ::: "memory");
    }
    for (int kb = 0; kb < kiters; ++kb) {
        asm volatile("cp.async.wait_group 2;" ::: "memory");
        __syncthreads();
        if (kb + 3 < kiters)
            issue1(Ah, lda, Bh, ldb, (kb + 3) * 16, sb + ((kb + 3) & 3) * STAGE1_B, tid);
        asm volatile("cp.async.commit_group;" ::: "memory");
        compute1(sb + (kb & 3) * STAGE1_B, lane, wm, wn, acc);
    }
}

// Fragment mapping: d0,d1 at (row g, col tq*2..+1); d2,d3 at row g+8.
#define EPILOG_VARS() \
    const int lane = threadIdx.x & 31; \
    const int wid = threadIdx.x >> 5;  \
    const int wm = wid & 1;            \
    const int wn = wid >> 1;           \
    const int g = lane >> 2;           \
    const int tq = lane & 3;

// ---------------------------------------------------------------------------
// Kernel 0a: split weights fp32 -> bf16 hi/lo
// ---------------------------------------------------------------------------
__global__ __launch_bounds__(256) void wsplit_kernel(
    const float* __restrict__ wq, const float* __restrict__ wk,
    const float* __restrict__ wv)
{
    const int idx = blockIdx.x * 256 + threadIdx.x;
    const int which = idx / (CC * CC);
    const int off = idx % (CC * CC);
    const float* src = (which == 0) ? wq : (which == 1) ? wk : wv;
    float v = src[off];
    __nv_bfloat16 h = __float2bfloat16(v);
    g_wh[idx] = h;
    g_wl[idx] = __float2bfloat16(v - __bfloat162float(h));
}

// ---------------------------------------------------------------------------
// Kernel 0b: transpose+split X[B,C,N] -> Xt hi/lo [B,N,C]
// ---------------------------------------------------------------------------
__global__ __launch_bounds__(256) void transpose_kernel(const float* __restrict__ x)
{
    __shared__ float t[32][33];
    const int b = blockIdx.z;
    const int n0 = blockIdx.x * 32;
    const int c0 = blockIdx.y * 32;
    const int tx = threadIdx.x & 31;
    const int ty = threadIdx.x >> 5;
    const float* X = x + (size_t)b * CC * NN;
    __nv_bfloat16* Xh = g_xth + (size_t)b * NN * CC;
    __nv_bfloat16* Xl = g_xtl + (size_t)b * NN * CC;
#pragma unroll
    for (int r = 0; r < 4; ++r)
        t[ty + r * 8][tx] = X[(size_t)(c0 + ty + r * 8) * NN + n0 + tx];
    __syncthreads();
#pragma unroll
    for (int r = 0; r < 4; ++r) {
        float v = t[tx][ty + r * 8];
        __nv_bfloat16 h = __float2bfloat16(v);
        const size_t o = (size_t)(n0 + ty + r * 8) * CC + c0 + tx;
        Xh[o] = h;
        Xl[o] = __float2bfloat16(v - __bfloat162float(h));
    }
}

// ---------------------------------------------------------------------------
// Kernel 1: QKV.  proj 0/1 (3-term): D[n,d]=Xt·W^T+b -> Qt/Kt hi/lo [n,d]
//                 proj 2   (1-term): D[d,n]=Wh·Xh^T+b -> V hi [d,n]
// ---------------------------------------------------------------------------
__global__ __launch_bounds__(256, 2) void qkv_kernel(
    const float* __restrict__ bq, const float* __restrict__ bk,
    const float* __restrict__ bv)
{
    __shared__ __align__(16) char smem[SMEM_TOT];
    const int z = blockIdx.z;
    const int b = z / 3, proj = z % 3;
    const float* bias = (proj == 0) ? bq : (proj == 1) ? bk : bv;
    const __nv_bfloat16* Wh = g_wh + (size_t)proj * CC * CC;
    const __nv_bfloat16* Wl = g_wl + (size_t)proj * CC * CC;
    const __nv_bfloat16* Xh = g_xth + (size_t)b * NN * CC;
    const __nv_bfloat16* Xl = g_xtl + (size_t)b * NN * CC;

    float acc[4][4][4] = {};

    if (proj < 2) {
        const int n0 = blockIdx.x * 128;
        const int d0 = blockIdx.y * 128;
        gemm3(Xh + (size_t)n0 * CC, Xl + (size_t)n0 * CC, CC,
              Wh + (size_t)d0 * CC, Wl + (size_t)d0 * CC, CC,
              CC / 16, smem, acc);
        EPILOG_VARS();
        __nv_bfloat16* dh = ((proj == 0) ? g_qth : g_kth) + (size_t)b * NN * CC;
        __nv_bfloat16* dl = ((proj == 0) ? g_qtl : g_ktl) + (size_t)b * NN * CC;
#pragma unroll
        for (int mt = 0; mt < 4; ++mt) {
            const int n = n0 + wm * 64 + mt * 16 + g;
#pragma unroll
            for (int nt = 0; nt < 4; ++nt) {
                const int d = d0 + wn * 32 + nt * 8 + tq * 2;
                const float2 bb = *(const float2*)(bias + d);
                __nv_bfloat162 h, l;
                split2(acc[mt][nt][0] + bb.x, acc[mt][nt][1] + bb.y, h, l);
                *(__nv_bfloat162*)(dh + (size_t)n * CC + d) = h;
                *(__nv_bfloat162*)(dl + (size_t)n * CC + d) = l;
                split2(acc[mt][nt][2] + bb.x, acc[mt][nt][3] + bb.y, h, l);
                *(__nv_bfloat162*)(dh + (size_t)(n + 8) * CC + d) = h;
                *(__nv_bfloat162*)(dl + (size_t)(n + 8) * CC + d) = l;
            }
        }
    } else {
        const int n0 = blockIdx.x * 128;
        const int d0 = blockIdx.y * 128;
        gemm1(Wh + (size_t)d0 * CC, CC, Xh + (size_t)n0 * CC, CC,
              CC / 16, smem, acc);
        EPILOG_VARS();
        __nv_bfloat16* dh = g_vh + (size_t)b * CC * NN;
#pragma unroll
        for (int mt = 0; mt < 4; ++mt) {
            const int d = d0 + wm * 64 + mt * 16 + g;
            const float b0 = bias[d], b1 = bias[d + 8];
#pragma unroll
            for (int nt = 0; nt < 4; ++nt) {
                const int n = n0 + wn * 32 + nt * 8 + tq * 2;
                *(__nv_bfloat162*)(dh + (size_t)d * NN + n) =
                    __floats2bfloat162_rn(acc[mt][nt][0] + b0, acc[mt][nt][1] + b0);
                *(__nv_bfloat162*)(dh + (size_t)(d + 8) * NN + n) =
                    __floats2bfloat162_rn(acc[mt][nt][2] + b1, acc[mt][nt][3] + b1);
            }
        }
    }
}

// ---------------------------------------------------------------------------
// Kernel 2: energy (3-term). D[i,j] = Qt·Kt^T -> E fp32 [i,j]
// ---------------------------------------------------------------------------
__global__ __launch_bounds__(256, 2) void energy_kernel()
{
    __shared__ __align__(16) char smem[SMEM_TOT];
    const int b = blockIdx.z;
    const int i0 = blockIdx.y * 128;
    const int j0 = blockIdx.x * 128;

    float acc[4][4][4] = {};
    gemm3(g_qth + ((size_t)b * NN + i0) * CC, g_qtl + ((size_t)b * NN + i0) * CC, CC,
          g_kth + ((size_t)b * NN + j0) * CC, g_ktl + ((size_t)b * NN + j0) * CC, CC,
          CC / 16, smem, acc);

    EPILOG_VARS();
    float* E = g_e + (size_t)b * NN * NN;
#pragma unroll
    for (int mt = 0; mt < 4; ++mt) {
        const int i = i0 + wm * 64 + mt * 16 + g;
#pragma unroll
        for (int nt = 0; nt < 4; ++nt) {
            const int j = j0 + wn * 32 + nt * 8 + tq * 2;
            *(float2*)(E + (size_t)i * NN + j) = make_float2(acc[mt][nt][0], acc[mt][nt][1]);
            *(float2*)(E + (size_t)(i + 8) * NN + j) = make_float2(acc[mt][nt][2], acc[mt][nt][3]);
        }
    }
}

// ---------------------------------------------------------------------------
// Kernel 3: row softmax, E fp32 -> P hi bf16
// ---------------------------------------------------------------------------
__global__ __launch_bounds__(256) void softmax_kernel()
{
    const size_t row = blockIdx.x;
    const float* p = g_e + row * (size_t)NN;
    __nv_bfloat162* ph = (__nv_bfloat162*)(g_ph + row * (size_t)NN);
    const int tid = threadIdx.x;

    float4 v[4];
    float mx = -1e30f;
#pragma unroll
    for (int t = 0; t < 4; ++t) {
        v[t] = ((const float4*)p)[tid + t * 256];
        mx = fmaxf(mx, fmaxf(fmaxf(v[t].x, v[t].y), fmaxf(v[t].z, v[t].w)));
    }
    __shared__ float red[8];
#pragma unroll
    for (int o = 16; o > 0; o >>= 1) mx = fmaxf(mx, __shfl_xor_sync(0xffffffffu, mx, o));
    if ((tid & 31) == 0) red[tid >> 5] = mx;
    __syncthreads();
    mx = red[0];
#pragma unroll
    for (int w = 1; w < 8; ++w) mx = fmaxf(mx, red[w]);
    __syncthreads();

    float sum = 0.f;
#pragma unroll
    for (int t = 0; t < 4; ++t) {
        v[t].x = __expf(v[t].x - mx); v[t].y = __expf(v[t].y - mx);
        v[t].z = __expf(v[t].z - mx); v[t].w = __expf(v[t].w - mx);
        sum += v[t].x + v[t].y + v[t].z + v[t].w;
    }
#pragma unroll
    for (int o = 16; o > 0; o >>= 1) sum += __shfl_xor_sync(0xffffffffu, sum, o);
    if ((tid & 31) == 0) red[tid >> 5] = sum;
    __syncthreads();
    sum = 0.f;
#pragma unroll
    for (int w = 0; w < 8; ++w) sum += red[w];

    const float inv = 1.0f / sum;
#pragma unroll
    for (int t = 0; t < 4; ++t) {
        const int o2 = (tid + t * 256) * 2;
        ph[o2]     = __floats2bfloat162_rn(v[t].x * inv, v[t].y * inv);
        ph[o2 + 1] = __floats2bfloat162_rn(v[t].z * inv, v[t].w * inv);
    }
}

// ---------------------------------------------------------------------------
// Kernel 4: VA + residual (1-term). D[c,i] = Vh·Ph^T -> out[c,i]
// ---------------------------------------------------------------------------
__global__ __launch_bounds__(256, 2) void va_kernel(
    const float* __restrict__ pose, const float* __restrict__ gamma,
    float* __restrict__ out)
{
    __shared__ __align__(16) char smem[SMEM_TOT];
    const int b = blockIdx.z;
    const int c0 = blockIdx.y * 128;
    const int i0 = blockIdx.x * 128;

    float acc[4][4][4] = {};
    gemm1(g_vh + ((size_t)b * CC + c0) * NN, NN,
          g_ph + ((size_t)b * NN + i0) * NN, NN,
          NN / 16, smem, acc);

    EPILOG_VARS();
    const float gm = gamma[0];
#pragma unroll
    for (int mt = 0; mt < 4; ++mt) {
        const int c = c0 + wm * 64 + mt * 16 + g;
#pragma unroll
        for (int nt = 0; nt < 4; ++nt) {
            const int i = i0 + wn * 32 + nt * 8 + tq * 2;
            const size_t i1 = ((size_t)b * CC + c) * NN + i;
            const size_t i2 = ((size_t)b * CC + c + 8) * NN + i;
            float2 p1 = *(const float2*)(pose + i1);
            float2 p2 = *(const float2*)(pose + i2);
            *(float2*)(out + i1) = make_float2(fmaf(gm, acc[mt][nt][0], p1.x),
                                               fmaf(gm, acc[mt][nt][1], p1.y));
            *(float2*)(out + i2) = make_float2(fmaf(gm, acc[mt][nt][2], p2.x),
                                               fmaf(gm, acc[mt][nt][3], p2.y));
        }
    }
}

// ---------------------------------------------------------------------------
extern "C" void kernel_launch(void* const* d_in, const int* in_sizes, int n_in,
                              void* d_out, int out_size)
{
    const float* pose  = (const float*)d_in[0];
    const float* wq    = (const float*)d_in[1];
    const float* bq    = (const float*)d_in[2];
    const float* wk    = (const float*)d_in[3];
    const float* bk    = (const float*)d_in[4];
    const float* wv    = (const float*)d_in[5];
    const float* bv    = (const float*)d_in[6];
    const float* gamma = (const float*)d_in[7];
    float* out = (float*)d_out;

    wsplit_kernel   <<<3 * CC * CC / 256, 256>>>(wq, wk, wv);
    transpose_kernel<<<dim3(NN / 32, CC / 32, BB), 256>>>(pose);
    qkv_kernel      <<<dim3(NN / 128, CC / 128, 3 * BB), 256>>>(bq, bk, bv);
    energy_kernel   <<<dim3(NN / 128, NN / 128, BB), 256>>>();
    softmax_kernel  <<<dim3(BB * NN), 256>>>();
    va_kernel       <<<dim3(NN / 128, CC / 128, BB), 256>>>(pose, gamma, out);
}

// round 16
// speedup vs baseline: 3.9802x; 1.0041x over previous
#include <cuda_runtime.h>
#include <cuda_bf16.h>
#include <cstdint>

#define BB 4
#define CC 256
#define NN 4096

// ---------------- scratch (__device__ globals; allocation-free rule) -------
__device__ __nv_bfloat16 g_xth[BB * NN * CC], g_xtl[BB * NN * CC];   // Xt [B,N,C]
__device__ __nv_bfloat16 g_qth[BB * NN * CC], g_qtl[BB * NN * CC];   // Qt [B,N,C]
__device__ __nv_bfloat16 g_kth[BB * NN * CC], g_ktl[BB * NN * CC];   // Kt [B,N,C]
__device__ __nv_bfloat16 g_vh [BB * CC * NN];                        // V  [B,C,N] (hi only)
__device__ __nv_bfloat16 g_wh [3 * CC * CC],  g_wl [3 * CC * CC];    // W split
__device__ float         g_e  [(size_t)BB * NN * NN];                // E fp32
__device__ __nv_bfloat16 g_ph [(size_t)BB * NN * NN];                // P hi only

// Tile = 128 rows x 16 bf16 = 32B/row = 2x16B chunks; swizzle chunk^=(row>>2)&1.
#define TILE_B    4096
#define STAGE3_B  (4 * TILE_B)   // Ahi, Alo, Bhi, Blo  (3-term path), 2 stages
#define STAGE1_B  (2 * TILE_B)   // Ah, Bh              (1-term path), 4 buffers
#define SMEM_TOT  32768          // 2 x STAGE3_B == 4 x STAGE1_B  (R13-proven)

static __device__ __forceinline__ uint32_t smem_u32(const void* p) {
    uint32_t a;
    asm("{ .reg .u64 t; cvta.to.shared.u64 t, %1; cvt.u32.u64 %0, t; }" : "=r"(a) : "l"(p));
    return a;
}
static __device__ __forceinline__ void cp16(uint32_t dst, const void* src) {
    asm volatile("cp.async.cg.shared.global [%0], [%1], 16;" :: "r"(dst), "l"(src));
}
static __device__ __forceinline__ void ldmx4(uint32_t& r0, uint32_t& r1, uint32_t& r2,
                                             uint32_t& r3, uint32_t addr) {
    asm volatile("ldmatrix.sync.aligned.m8n8.x4.shared.b16 {%0,%1,%2,%3}, [%4];"
                 : "=r"(r0), "=r"(r1), "=r"(r2), "=r"(r3) : "r"(addr));
}
static __device__ __forceinline__ void mma16816(float* d, uint32_t a0, uint32_t a1,
                                                uint32_t a2, uint32_t a3,
                                                uint32_t b0, uint32_t b1) {
    asm volatile(
        "mma.sync.aligned.m16n8k16.row.col.f32.bf16.bf16.f32 "
        "{%0,%1,%2,%3}, {%4,%5,%6,%7}, {%8,%9}, {%0,%1,%2,%3};"
        : "+f"(d[0]), "+f"(d[1]), "+f"(d[2]), "+f"(d[3])
        : "r"(a0), "r"(a1), "r"(a2), "r"(a3), "r"(b0), "r"(b1));
}
static __device__ __forceinline__ void split2(float x, float y,
                                              __nv_bfloat162& h, __nv_bfloat162& l) {
    h = __floats2bfloat162_rn(x, y);
    float2 f = __bfloat1622float2(h);
    l = __floats2bfloat162_rn(x - f.x, y - f.y);
}

// B-fragment loader: one ldmx4 covers an nt-pair (rows +0/+8) x both k-halves.
#define B_PAIR_OFF(base_row, lane, p) \
    ((((base_row) + (p) * 16 + (((lane) >> 4) & 1) * 8 + ((lane) & 7)) * 32) + \
     (((((lane) >> 3) & 1) ^ ((((lane) & 7) >> 2) & 1)) * 16))

// ---------------------- 3-term pipeline (2 stages, 1 barrier/stage) --------
static __device__ __forceinline__ void issue3(
    const __nv_bfloat16* __restrict__ Ahi, const __nv_bfloat16* __restrict__ Alo, int lda,
    const __nv_bfloat16* __restrict__ Bhi, const __nv_bfloat16* __restrict__ Blo, int ldb,
    int k0, uint32_t st, int tid)
{
    const int row = tid >> 1;
    const int chunk = tid & 1;
    const uint32_t dsto = row * 32 + ((chunk ^ ((row >> 2) & 1)) * 16);
    const size_t asrc = (size_t)row * lda + k0 + chunk * 8;
    const size_t bsrc = (size_t)row * ldb + k0 + chunk * 8;
    cp16(st + dsto,              Ahi + asrc);
    cp16(st + TILE_B + dsto,     Alo + asrc);
    cp16(st + 2 * TILE_B + dsto, Bhi + bsrc);
    cp16(st + 3 * TILE_B + dsto, Blo + bsrc);
}

static __device__ __forceinline__ void compute3(
    uint32_t st, int lane, int wm, int wn, float acc[4][4][4])
{
    const uint32_t rowA = wm * 64 + (lane & 15);
    const uint32_t cA = ((lane >> 4) & 1) ^ (((lane & 15) >> 2) & 1);

    uint32_t bh[4][2], bl[4][2];
#pragma unroll
    for (int p = 0; p < 2; ++p) {
        const uint32_t bo = B_PAIR_OFF(wn * 32, lane, p);
        ldmx4(bh[2 * p][0], bh[2 * p][1], bh[2 * p + 1][0], bh[2 * p + 1][1],
              st + 2 * TILE_B + bo);
        ldmx4(bl[2 * p][0], bl[2 * p][1], bl[2 * p + 1][0], bl[2 * p + 1][1],
              st + 3 * TILE_B + bo);
    }
#pragma unroll
    for (int mt = 0; mt < 4; ++mt) {
        const uint32_t ao = (rowA + mt * 16) * 32 + cA * 16;
        uint32_t ah0, ah1, ah2, ah3, al0, al1, al2, al3;
        ldmx4(ah0, ah1, ah2, ah3, st + ao);
        ldmx4(al0, al1, al2, al3, st + TILE_B + ao);
#pragma unroll
        for (int nt = 0; nt < 4; ++nt) {
            mma16816(acc[mt][nt], ah0, ah1, ah2, ah3, bh[nt][0], bh[nt][1]);
            mma16816(acc[mt][nt], ah0, ah1, ah2, ah3, bl[nt][0], bl[nt][1]);
            mma16816(acc[mt][nt], al0, al1, al2, al3, bh[nt][0], bh[nt][1]);
        }
    }
}

static __device__ __forceinline__ void gemm3(
    const __nv_bfloat16* __restrict__ Ahi, const __nv_bfloat16* __restrict__ Alo, int lda,
    const __nv_bfloat16* __restrict__ Bhi, const __nv_bfloat16* __restrict__ Blo, int ldb,
    int kiters, char* smem, float acc[4][4][4])
{
    const int tid = threadIdx.x;
    const int lane = tid & 31, wid = tid >> 5;
    const int wm = wid & 1, wn = wid >> 1;
    const uint32_t sb = smem_u32(smem);

    issue3(Ahi, Alo, lda, Bhi, Blo, ldb, 0, sb, tid);
    asm volatile("cp.async.commit_group;" ::: "memory");
    // wait(kb) -> barrier -> issue(kb+1) -> commit -> compute(kb).   (R13-proven)
    for (int kb = 0; kb < kiters; ++kb) {
        asm volatile("cp.async.wait_group 0;" ::: "memory");
        __syncthreads();
        if (kb + 1 < kiters)
            issue3(Ahi, Alo, lda, Bhi, Blo, ldb, (kb + 1) * 16,
                   sb + ((kb + 1) & 1) * STAGE3_B, tid);
        asm volatile("cp.async.commit_group;" ::: "memory");
        compute3(sb + (kb & 1) * STAGE3_B, lane, wm, wn, acc);
    }
}

// ------ 1-term pipeline (4 buffers, 1 barrier/stage; R12/R13-proven) -------
static __device__ __forceinline__ void issue1(
    const __nv_bfloat16* __restrict__ Ah, int lda,
    const __nv_bfloat16* __restrict__ Bh, int ldb,
    int k0, uint32_t st, int tid)
{
    const int row = tid >> 1;
    const int chunk = tid & 1;
    const uint32_t dsto = row * 32 + ((chunk ^ ((row >> 2) & 1)) * 16);
    cp16(st + dsto,          Ah + (size_t)row * lda + k0 + chunk * 8);
    cp16(st + TILE_B + dsto, Bh + (size_t)row * ldb + k0 + chunk * 8);
}

static __device__ __forceinline__ void compute1(
    uint32_t st, int lane, int wm, int wn, float acc[4][4][4])
{
    const uint32_t rowA = wm * 64 + (lane & 15);
    const uint32_t cA = ((lane >> 4) & 1) ^ (((lane & 15) >> 2) & 1);

    uint32_t bh[4][2];
#pragma unroll
    for (int p = 0; p < 2; ++p) {
        const uint32_t bo = B_PAIR_OFF(wn * 32, lane, p);
        ldmx4(bh[2 * p][0], bh[2 * p][1], bh[2 * p + 1][0], bh[2 * p + 1][1],
              st + TILE_B + bo);
    }
#pragma unroll
    for (int mt = 0; mt < 4; ++mt) {
        const uint32_t ao = (rowA + mt * 16) * 32 + cA * 16;
        uint32_t a0, a1, a2, a3;
        ldmx4(a0, a1, a2, a3, st + ao);
#pragma unroll
        for (int nt = 0; nt < 4; ++nt)
            mma16816(acc[mt][nt], a0, a1, a2, a3, bh[nt][0], bh[nt][1]);
    }
}

static __device__ __forceinline__ void gemm1(
    const __nv_bfloat16* __restrict__ Ah, int lda,
    const __nv_bfloat16* __restrict__ Bh, int ldb,
    int kiters, char* smem, float acc[4][4][4])
{
    const int tid = threadIdx.x;
    const int lane = tid & 31, wid = tid >> 5;
    const int wm = wid & 1, wn = wid >> 1;
    const uint32_t sb = smem_u32(smem);

#pragma unroll
    for (int s = 0; s < 3; ++s) {
        issue1(Ah, lda, Bh, ldb, s * 16, sb + s * STAGE1_B, tid);
        asm volatile("cp.async.commit_group;" ::: "memory");
    }
    for (int kb = 0; kb < kiters; ++kb) {
        asm volatile("cp.async.wait_group 2;" ::: "memory");
        __syncthreads();
        if (kb + 3 < kiters)
            issue1(Ah, lda, Bh, ldb, (kb + 3) * 16, sb + ((kb + 3) & 3) * STAGE1_B, tid);
        asm volatile("cp.async.commit_group;" ::: "memory");
        compute1(sb + (kb & 3) * STAGE1_B, lane, wm, wn, acc);
    }
}

// Fragment mapping: d0,d1 at (row g, col tq*2..+1); d2,d3 at row g+8.
#define EPILOG_VARS() \
    const int lane = threadIdx.x & 31; \
    const int wid = threadIdx.x >> 5;  \
    const int wm = wid & 1;            \
    const int wn = wid >> 1;           \
    const int g = lane >> 2;           \
    const int tq = lane & 3;

// ---------------------------------------------------------------------------
// Kernel 0a: split weights fp32 -> bf16 hi/lo
// ---------------------------------------------------------------------------
__global__ __launch_bounds__(256) void wsplit_kernel(
    const float* __restrict__ wq, const float* __restrict__ wk,
    const float* __restrict__ wv)
{
    const int idx = blockIdx.x * 256 + threadIdx.x;
    const int which = idx / (CC * CC);
    const int off = idx % (CC * CC);
    const float* src = (which == 0) ? wq : (which == 1) ? wk : wv;
    float v = src[off];
    __nv_bfloat16 h = __float2bfloat16(v);
    g_wh[idx] = h;
    g_wl[idx] = __float2bfloat16(v - __bfloat162float(h));
}

// ---------------------------------------------------------------------------
// Kernel 0b: transpose+split X[B,C,N] -> Xt hi/lo [B,N,C]
// ---------------------------------------------------------------------------
__global__ __launch_bounds__(256) void transpose_kernel(const float* __restrict__ x)
{
    __shared__ float t[32][33];
    const int b = blockIdx.z;
    const int n0 = blockIdx.x * 32;
    const int c0 = blockIdx.y * 32;
    const int tx = threadIdx.x & 31;
    const int ty = threadIdx.x >> 5;
    const float* X = x + (size_t)b * CC * NN;
    __nv_bfloat16* Xh = g_xth + (size_t)b * NN * CC;
    __nv_bfloat16* Xl = g_xtl + (size_t)b * NN * CC;
#pragma unroll
    for (int r = 0; r < 4; ++r)
        t[ty + r * 8][tx] = X[(size_t)(c0 + ty + r * 8) * NN + n0 + tx];
    __syncthreads();
#pragma unroll
    for (int r = 0; r < 4; ++r) {
        float v = t[tx][ty + r * 8];
        __nv_bfloat16 h = __float2bfloat16(v);
        const size_t o = (size_t)(n0 + ty + r * 8) * CC + c0 + tx;
        Xh[o] = h;
        Xl[o] = __float2bfloat16(v - __bfloat162float(h));
    }
}

// ---------------------------------------------------------------------------
// Kernel 1: QKV.  proj 0/1 (3-term): D[n,d]=Xt·W^T+b -> Qt/Kt hi/lo [n,d]
//                 proj 2   (1-term): D[d,n]=Wh·Xh^T+b -> V hi [d,n]
// ---------------------------------------------------------------------------
__global__ __launch_bounds__(256, 2) void qkv_kernel(
    const float* __restrict__ bq, const float* __restrict__ bk,
    const float* __restrict__ bv)
{
    __shared__ __align__(16) char smem[SMEM_TOT];
    const int z = blockIdx.z;
    const int b = z / 3, proj = z % 3;
    const float* bias = (proj == 0) ? bq : (proj == 1) ? bk : bv;
    const __nv_bfloat16* Wh = g_wh + (size_t)proj * CC * CC;
    const __nv_bfloat16* Wl = g_wl + (size_t)proj * CC * CC;
    const __nv_bfloat16* Xh = g_xth + (size_t)b * NN * CC;
    const __nv_bfloat16* Xl = g_xtl + (size_t)b * NN * CC;

    float acc[4][4][4] = {};

    if (proj < 2) {
        const int n0 = blockIdx.x * 128;
        const int d0 = blockIdx.y * 128;
        gemm3(Xh + (size_t)n0 * CC, Xl + (size_t)n0 * CC, CC,
              Wh + (size_t)d0 * CC, Wl + (size_t)d0 * CC, CC,
              CC / 16, smem, acc);
        EPILOG_VARS();
        __nv_bfloat16* dh = ((proj == 0) ? g_qth : g_kth) + (size_t)b * NN * CC;
        __nv_bfloat16* dl = ((proj == 0) ? g_qtl : g_ktl) + (size_t)b * NN * CC;
#pragma unroll
        for (int mt = 0; mt < 4; ++mt) {
            const int n = n0 + wm * 64 + mt * 16 + g;
#pragma unroll
            for (int nt = 0; nt < 4; ++nt) {
                const int d = d0 + wn * 32 + nt * 8 + tq * 2;
                const float2 bb = *(const float2*)(bias + d);
                __nv_bfloat162 h, l;
                split2(acc[mt][nt][0] + bb.x, acc[mt][nt][1] + bb.y, h, l);
                *(__nv_bfloat162*)(dh + (size_t)n * CC + d) = h;
                *(__nv_bfloat162*)(dl + (size_t)n * CC + d) = l;
                split2(acc[mt][nt][2] + bb.x, acc[mt][nt][3] + bb.y, h, l);
                *(__nv_bfloat162*)(dh + (size_t)(n + 8) * CC + d) = h;
                *(__nv_bfloat162*)(dl + (size_t)(n + 8) * CC + d) = l;
            }
        }
    } else {
        const int n0 = blockIdx.x * 128;
        const int d0 = blockIdx.y * 128;
        gemm1(Wh + (size_t)d0 * CC, CC, Xh + (size_t)n0 * CC, CC,
              CC / 16, smem, acc);
        EPILOG_VARS();
        __nv_bfloat16* dh = g_vh + (size_t)b * CC * NN;
#pragma unroll
        for (int mt = 0; mt < 4; ++mt) {
            const int d = d0 + wm * 64 + mt * 16 + g;
            const float b0 = bias[d], b1 = bias[d + 8];
#pragma unroll
            for (int nt = 0; nt < 4; ++nt) {
                const int n = n0 + wn * 32 + nt * 8 + tq * 2;
                *(__nv_bfloat162*)(dh + (size_t)d * NN + n) =
                    __floats2bfloat162_rn(acc[mt][nt][0] + b0, acc[mt][nt][1] + b0);
                *(__nv_bfloat162*)(dh + (size_t)(d + 8) * NN + n) =
                    __floats2bfloat162_rn(acc[mt][nt][2] + b1, acc[mt][nt][3] + b1);
            }
        }
    }
}

// ---------------------------------------------------------------------------
// Kernel 2: energy (3-term). D[i,j] = Qt·Kt^T -> E fp32 [i,j]
// E is written once and read once by softmax (working set >> L2): stream it.
// ---------------------------------------------------------------------------
__global__ __launch_bounds__(256, 2) void energy_kernel()
{
    __shared__ __align__(16) char smem[SMEM_TOT];
    const int b = blockIdx.z;
    const int i0 = blockIdx.y * 128;
    const int j0 = blockIdx.x * 128;

    float acc[4][4][4] = {};
    gemm3(g_qth + ((size_t)b * NN + i0) * CC, g_qtl + ((size_t)b * NN + i0) * CC, CC,
          g_kth + ((size_t)b * NN + j0) * CC, g_ktl + ((size_t)b * NN + j0) * CC, CC,
          CC / 16, smem, acc);

    EPILOG_VARS();
    float* E = g_e + (size_t)b * NN * NN;
#pragma unroll
    for (int mt = 0; mt < 4; ++mt) {
        const int i = i0 + wm * 64 + mt * 16 + g;
#pragma unroll
        for (int nt = 0; nt < 4; ++nt) {
            const int j = j0 + wn * 32 + nt * 8 + tq * 2;
            __stcs((float2*)(E + (size_t)i * NN + j),
                   make_float2(acc[mt][nt][0], acc[mt][nt][1]));
            __stcs((float2*)(E + (size_t)(i + 8) * NN + j),
                   make_float2(acc[mt][nt][2], acc[mt][nt][3]));
        }
    }
}

// ---------------------------------------------------------------------------
// Kernel 3: row softmax, E fp32 -> P hi bf16. Streaming on both sides.
// ---------------------------------------------------------------------------
__global__ __launch_bounds__(256) void softmax_kernel()
{
    const size_t row = blockIdx.x;
    const float* p = g_e + row * (size_t)NN;
    uint2* ph2 = (uint2*)(g_ph + row * (size_t)NN);   // 2 x bf16x2 per uint2
    const int tid = threadIdx.x;

    float4 v[4];
    float mx = -1e30f;
#pragma unroll
    for (int t = 0; t < 4; ++t) {
        v[t] = __ldcs(&((const float4*)p)[tid + t * 256]);
        mx = fmaxf(mx, fmaxf(fmaxf(v[t].x, v[t].y), fmaxf(v[t].z, v[t].w)));
    }
    __shared__ float red[8];
#pragma unroll
    for (int o = 16; o > 0; o >>= 1) mx = fmaxf(mx, __shfl_xor_sync(0xffffffffu, mx, o));
    if ((tid & 31) == 0) red[tid >> 5] = mx;
    __syncthreads();
    mx = red[0];
#pragma unroll
    for (int w = 1; w < 8; ++w) mx = fmaxf(mx, red[w]);
    __syncthreads();

    float sum = 0.f;
#pragma unroll
    for (int t = 0; t < 4; ++t) {
        v[t].x = __expf(v[t].x - mx); v[t].y = __expf(v[t].y - mx);
        v[t].z = __expf(v[t].z - mx); v[t].w = __expf(v[t].w - mx);
        sum += v[t].x + v[t].y + v[t].z + v[t].w;
    }
#pragma unroll
    for (int o = 16; o > 0; o >>= 1) sum += __shfl_xor_sync(0xffffffffu, sum, o);
    if ((tid & 31) == 0) red[tid >> 5] = sum;
    __syncthreads();
    sum = 0.f;
#pragma unroll
    for (int w = 0; w < 8; ++w) sum += red[w];

    const float inv = 1.0f / sum;
#pragma unroll
    for (int t = 0; t < 4; ++t) {
        __nv_bfloat162 h0 = __floats2bfloat162_rn(v[t].x * inv, v[t].y * inv);
        __nv_bfloat162 h1 = __floats2bfloat162_rn(v[t].z * inv, v[t].w * inv);
        uint2 pk;
        pk.x = *(uint32_t*)&h0;
        pk.y = *(uint32_t*)&h1;
        __stcs(&ph2[tid + t * 256], pk);
    }
}

// ---------------------------------------------------------------------------
// Kernel 4: VA + residual (1-term). D[c,i] = Vh·Ph^T -> out[c,i]
// ---------------------------------------------------------------------------
__global__ __launch_bounds__(256, 2) void va_kernel(
    const float* __restrict__ pose, const float* __restrict__ gamma,
    float* __restrict__ out)
{
    __shared__ __align__(16) char smem[SMEM_TOT];
    const int b = blockIdx.z;
    const int c0 = blockIdx.y * 128;
    const int i0 = blockIdx.x * 128;

    float acc[4][4][4] = {};
    gemm1(g_vh + ((size_t)b * CC + c0) * NN, NN,
          g_ph + ((size_t)b * NN + i0) * NN, NN,
          NN / 16, smem, acc);

    EPILOG_VARS();
    const float gm = gamma[0];
#pragma unroll
    for (int mt = 0; mt < 4; ++mt) {
        const int c = c0 + wm * 64 + mt * 16 + g;
#pragma unroll
        for (int nt = 0; nt < 4; ++nt) {
            const int i = i0 + wn * 32 + nt * 8 + tq * 2;
            const size_t i1 = ((size_t)b * CC + c) * NN + i;
            const size_t i2 = ((size_t)b * CC + c + 8) * NN + i;
            float2 p1 = *(const float2*)(pose + i1);
            float2 p2 = *(const float2*)(pose + i2);
            *(float2*)(out + i1) = make_float2(fmaf(gm, acc[mt][nt][0], p1.x),
                                               fmaf(gm, acc[mt][nt][1], p1.y));
            *(float2*)(out + i2) = make_float2(fmaf(gm, acc[mt][nt][2], p2.x),
                                               fmaf(gm, acc[mt][nt][3], p2.y));
        }
    }
}

// ---------------------------------------------------------------------------
extern "C" void kernel_launch(void* const* d_in, const int* in_sizes, int n_in,
                              void* d_out, int out_size)
{
    const float* pose  = (const float*)d_in[0];
    const float* wq    = (const float*)d_in[1];
    const float* bq    = (const float*)d_in[2];
    const float* wk    = (const float*)d_in[3];
    const float* bk    = (const float*)d_in[4];
    const float* wv    = (const float*)d_in[5];
    const float* bv    = (const float*)d_in[6];
    const float* gamma = (const float*)d_in[7];
    float* out = (float*)d_out;

    wsplit_kernel   <<<3 * CC * CC / 256, 256>>>(wq, wk, wv);
    transpose_kernel<<<dim3(NN / 32, CC / 32, BB), 256>>>(pose);
    qkv_kernel      <<<dim3(NN / 128, CC / 128, 3 * BB), 256>>>(bq, bk, bv);
    energy_kernel   <<<dim3(NN / 128, NN / 128, BB), 256>>>();
    softmax_kernel  <<<dim3(BB * NN), 256>>>();
    va_kernel       <<<dim3(NN / 128, CC / 128, BB), 256>>>(pose, gamma, out);
}

// round 17
// speedup vs baseline: 4.5861x; 1.1522x over previous
#include <cuda_runtime.h>
#include <cuda_fp16.h>
#include <cstdint>

#define BB 4
#define CC 256
#define NN 4096

// ---------------- scratch (__device__ globals; allocation-free rule) -------
__device__ __half g_xth[BB * NN * CC], g_xtl[BB * NN * CC];   // Xt [B,N,C]
__device__ __half g_qth[BB * NN * CC];                        // Qt hi only [B,N,C]
__device__ __half g_kth[BB * NN * CC], g_ktl[BB * NN * CC];   // Kt hi/lo [B,N,C]
__device__ __half g_vh [BB * CC * NN];                        // V  [B,C,N] (hi only)
__device__ __half g_wh [3 * CC * CC],  g_wl [3 * CC * CC];    // W split
__device__ float  g_e  [(size_t)BB * NN * NN];                // E fp32
__device__ __half g_ph [(size_t)BB * NN * NN];                // P hi only

// Tile = 128 rows x 16 fp16 = 32B/row = 2x16B chunks; swizzle chunk^=(row>>2)&1.
#define TILE_B    4096
#define STAGE3_B  (4 * TILE_B)   // Ahi, Alo, Bhi, Blo  (3-term proj path), 2 stages
#define STAGE2_B  (3 * TILE_B)   // Ah, Bh, Bl          (2-term energy path), 2 stages
#define STAGE1_B  (2 * TILE_B)   // Ah, Bh              (1-term path), 4 buffers
#define SMEM_TOT3 32768          // 2 x STAGE3_B == 4 x STAGE1_B (proven)
#define SMEM_TOT2 24576          // 2 x STAGE2_B

static __device__ __forceinline__ uint32_t smem_u32(const void* p) {
    uint32_t a;
    asm("{ .reg .u64 t; cvta.to.shared.u64 t, %1; cvt.u32.u64 %0, t; }" : "=r"(a) : "l"(p));
    return a;
}
static __device__ __forceinline__ void cp16(uint32_t dst, const void* src) {
    asm volatile("cp.async.cg.shared.global [%0], [%1], 16;" :: "r"(dst), "l"(src));
}
static __device__ __forceinline__ void ldmx4(uint32_t& r0, uint32_t& r1, uint32_t& r2,
                                             uint32_t& r3, uint32_t addr) {
    asm volatile("ldmatrix.sync.aligned.m8n8.x4.shared.b16 {%0,%1,%2,%3}, [%4];"
                 : "=r"(r0), "=r"(r1), "=r"(r2), "=r"(r3) : "r"(addr));
}
static __device__ __forceinline__ void mma16816(float* d, uint32_t a0, uint32_t a1,
                                                uint32_t a2, uint32_t a3,
                                                uint32_t b0, uint32_t b1) {
    asm volatile(
        "mma.sync.aligned.m16n8k16.row.col.f32.f16.f16.f32 "
        "{%0,%1,%2,%3}, {%4,%5,%6,%7}, {%8,%9}, {%0,%1,%2,%3};"
        : "+f"(d[0]), "+f"(d[1]), "+f"(d[2]), "+f"(d[3])
        : "r"(a0), "r"(a1), "r"(a2), "r"(a3), "r"(b0), "r"(b1));
}
static __device__ __forceinline__ void split2(float x, float y, __half2& h, __half2& l) {
    h = __floats2half2_rn(x, y);
    float2 f = __half22float2(h);
    l = __floats2half2_rn(x - f.x, y - f.y);
}

// B-fragment loader: one ldmx4 covers an nt-pair (rows +0/+8) x both k-halves.
#define B_PAIR_OFF(base_row, lane, p) \
    ((((base_row) + (p) * 16 + (((lane) >> 4) & 1) * 8 + ((lane) & 7)) * 32) + \
     (((((lane) >> 3) & 1) ^ ((((lane) & 7) >> 2) & 1)) * 16))

// ---------------------- 3-term pipeline (2 stages, 1 barrier/stage) --------
static __device__ __forceinline__ void issue3(
    const __half* __restrict__ Ahi, const __half* __restrict__ Alo, int lda,
    const __half* __restrict__ Bhi, const __half* __restrict__ Blo, int ldb,
    int k0, uint32_t st, int tid)
{
    const int row = tid >> 1;
    const int chunk = tid & 1;
    const uint32_t dsto = row * 32 + ((chunk ^ ((row >> 2) & 1)) * 16);
    const size_t asrc = (size_t)row * lda + k0 + chunk * 8;
    const size_t bsrc = (size_t)row * ldb + k0 + chunk * 8;
    cp16(st + dsto,              Ahi + asrc);
    cp16(st + TILE_B + dsto,     Alo + asrc);
    cp16(st + 2 * TILE_B + dsto, Bhi + bsrc);
    cp16(st + 3 * TILE_B + dsto, Blo + bsrc);
}

static __device__ __forceinline__ void compute3(
    uint32_t st, int lane, int wm, int wn, float acc[4][4][4])
{
    const uint32_t rowA = wm * 64 + (lane & 15);
    const uint32_t cA = ((lane >> 4) & 1) ^ (((lane & 15) >> 2) & 1);

    uint32_t bh[4][2], bl[4][2];
#pragma unroll
    for (int p = 0; p < 2; ++p) {
        const uint32_t bo = B_PAIR_OFF(wn * 32, lane, p);
        ldmx4(bh[2 * p][0], bh[2 * p][1], bh[2 * p + 1][0], bh[2 * p + 1][1],
              st + 2 * TILE_B + bo);
        ldmx4(bl[2 * p][0], bl[2 * p][1], bl[2 * p + 1][0], bl[2 * p + 1][1],
              st + 3 * TILE_B + bo);
    }
#pragma unroll
    for (int mt = 0; mt < 4; ++mt) {
        const uint32_t ao = (rowA + mt * 16) * 32 + cA * 16;
        uint32_t ah0, ah1, ah2, ah3, al0, al1, al2, al3;
        ldmx4(ah0, ah1, ah2, ah3, st + ao);
        ldmx4(al0, al1, al2, al3, st + TILE_B + ao);
#pragma unroll
        for (int nt = 0; nt < 4; ++nt) {
            mma16816(acc[mt][nt], ah0, ah1, ah2, ah3, bh[nt][0], bh[nt][1]);
            mma16816(acc[mt][nt], ah0, ah1, ah2, ah3, bl[nt][0], bl[nt][1]);
            mma16816(acc[mt][nt], al0, al1, al2, al3, bh[nt][0], bh[nt][1]);
        }
    }
}

static __device__ __forceinline__ void gemm3(
    const __half* __restrict__ Ahi, const __half* __restrict__ Alo, int lda,
    const __half* __restrict__ Bhi, const __half* __restrict__ Blo, int ldb,
    int kiters, char* smem, float acc[4][4][4])
{
    const int tid = threadIdx.x;
    const int lane = tid & 31, wid = tid >> 5;
    const int wm = wid & 1, wn = wid >> 1;
    const uint32_t sb = smem_u32(smem);

    issue3(Ahi, Alo, lda, Bhi, Blo, ldb, 0, sb, tid);
    asm volatile("cp.async.commit_group;" ::: "memory");
    for (int kb = 0; kb < kiters; ++kb) {
        asm volatile("cp.async.wait_group 0;" ::: "memory");
        __syncthreads();
        if (kb + 1 < kiters)
            issue3(Ahi, Alo, lda, Bhi, Blo, ldb, (kb + 1) * 16,
                   sb + ((kb + 1) & 1) * STAGE3_B, tid);
        asm volatile("cp.async.commit_group;" ::: "memory");
        compute3(sb + (kb & 1) * STAGE3_B, lane, wm, wn, acc);
    }
}

// ----- 2-term pipeline (2 stages, 1 barrier/stage; same proven skeleton) ---
static __device__ __forceinline__ void issue2(
    const __half* __restrict__ Ah, int lda,
    const __half* __restrict__ Bh, const __half* __restrict__ Bl, int ldb,
    int k0, uint32_t st, int tid)
{
    const int row = tid >> 1;
    const int chunk = tid & 1;
    const uint32_t dsto = row * 32 + ((chunk ^ ((row >> 2) & 1)) * 16);
    const size_t asrc = (size_t)row * lda + k0 + chunk * 8;
    const size_t bsrc = (size_t)row * ldb + k0 + chunk * 8;
    cp16(st + dsto,              Ah + asrc);
    cp16(st + TILE_B + dsto,     Bh + bsrc);
    cp16(st + 2 * TILE_B + dsto, Bl + bsrc);
}

static __device__ __forceinline__ void compute2(
    uint32_t st, int lane, int wm, int wn, float acc[4][4][4])
{
    const uint32_t rowA = wm * 64 + (lane & 15);
    const uint32_t cA = ((lane >> 4) & 1) ^ (((lane & 15) >> 2) & 1);

    uint32_t bh[4][2], bl[4][2];
#pragma unroll
    for (int p = 0; p < 2; ++p) {
        const uint32_t bo = B_PAIR_OFF(wn * 32, lane, p);
        ldmx4(bh[2 * p][0], bh[2 * p][1], bh[2 * p + 1][0], bh[2 * p + 1][1],
              st + TILE_B + bo);
        ldmx4(bl[2 * p][0], bl[2 * p][1], bl[2 * p + 1][0], bl[2 * p + 1][1],
              st + 2 * TILE_B + bo);
    }
#pragma unroll
    for (int mt = 0; mt < 4; ++mt) {
        const uint32_t ao = (rowA + mt * 16) * 32 + cA * 16;
        uint32_t a0, a1, a2, a3;
        ldmx4(a0, a1, a2, a3, st + ao);
#pragma unroll
        for (int nt = 0; nt < 4; ++nt) {
            mma16816(acc[mt][nt], a0, a1, a2, a3, bh[nt][0], bh[nt][1]);
            mma16816(acc[mt][nt], a0, a1, a2, a3, bl[nt][0], bl[nt][1]);
        }
    }
}

static __device__ __forceinline__ void gemm2(
    const __half* __restrict__ Ah, int lda,
    const __half* __restrict__ Bh, const __half* __restrict__ Bl, int ldb,
    int kiters, char* smem, float acc[4][4][4])
{
    const int tid = threadIdx.x;
    const int lane = tid & 31, wid = tid >> 5;
    const int wm = wid & 1, wn = wid >> 1;
    const uint32_t sb = smem_u32(smem);

    issue2(Ah, lda, Bh, Bl, ldb, 0, sb, tid);
    asm volatile("cp.async.commit_group;" ::: "memory");
    for (int kb = 0; kb < kiters; ++kb) {
        asm volatile("cp.async.wait_group 0;" ::: "memory");
        __syncthreads();
        if (kb + 1 < kiters)
            issue2(Ah, lda, Bh, Bl, ldb, (kb + 1) * 16,
                   sb + ((kb + 1) & 1) * STAGE2_B, tid);
        asm volatile("cp.async.commit_group;" ::: "memory");
        compute2(sb + (kb & 1) * STAGE2_B, lane, wm, wn, acc);
    }
}

// ------ 1-term pipeline (4 buffers, 1 barrier/stage; R12/R13-proven) -------
static __device__ __forceinline__ void issue1(
    const __half* __restrict__ Ah, int lda,
    const __half* __restrict__ Bh, int ldb,
    int k0, uint32_t st, int tid)
{
    const int row = tid >> 1;
    const int chunk = tid & 1;
    const uint32_t dsto = row * 32 + ((chunk ^ ((row >> 2) & 1)) * 16);
    cp16(st + dsto,          Ah + (size_t)row * lda + k0 + chunk * 8);
    cp16(st + TILE_B + dsto, Bh + (size_t)row * ldb + k0 + chunk * 8);
}

static __device__ __forceinline__ void compute1(
    uint32_t st, int lane, int wm, int wn, float acc[4][4][4])
{
    const uint32_t rowA = wm * 64 + (lane & 15);
    const uint32_t cA = ((lane >> 4) & 1) ^ (((lane & 15) >> 2) & 1);

    uint32_t bh[4][2];
#pragma unroll
    for (int p = 0; p < 2; ++p) {
        const uint32_t bo = B_PAIR_OFF(wn * 32, lane, p);
        ldmx4(bh[2 * p][0], bh[2 * p][1], bh[2 * p + 1][0], bh[2 * p + 1][1],
              st + TILE_B + bo);
    }
#pragma unroll
    for (int mt = 0; mt < 4; ++mt) {
        const uint32_t ao = (rowA + mt * 16) * 32 + cA * 16;
        uint32_t a0, a1, a2, a3;
        ldmx4(a0, a1, a2, a3, st + ao);
#pragma unroll
        for (int nt = 0; nt < 4; ++nt)
            mma16816(acc[mt][nt], a0, a1, a2, a3, bh[nt][0], bh[nt][1]);
    }
}

static __device__ __forceinline__ void gemm1(
    const __half* __restrict__ Ah, int lda,
    const __half* __restrict__ Bh, int ldb,
    int kiters, char* smem, float acc[4][4][4])
{
    const int tid = threadIdx.x;
    const int lane = tid & 31, wid = tid >> 5;
    const int wm = wid & 1, wn = wid >> 1;
    const uint32_t sb = smem_u32(smem);

#pragma unroll
    for (int s = 0; s < 3; ++s) {
        issue1(Ah, lda, Bh, ldb, s * 16, sb + s * STAGE1_B, tid);
        asm volatile("cp.async.commit_group;" ::: "memory");
    }
    for (int kb = 0; kb < kiters; ++kb) {
        asm volatile("cp.async.wait_group 2;" ::: "memory");
        __syncthreads();
        if (kb + 3 < kiters)
            issue1(Ah, lda, Bh, ldb, (kb + 3) * 16, sb + ((kb + 3) & 3) * STAGE1_B, tid);
        asm volatile("cp.async.commit_group;" ::: "memory");
        compute1(sb + (kb & 3) * STAGE1_B, lane, wm, wn, acc);
    }
}

// Fragment mapping: d0,d1 at (row g, col tq*2..+1); d2,d3 at row g+8.
#define EPILOG_VARS() \
    const int lane = threadIdx.x & 31; \
    const int wid = threadIdx.x >> 5;  \
    const int wm = wid & 1;            \
    const int wn = wid >> 1;           \
    const int g = lane >> 2;           \
    const int tq = lane & 3;

// ---------------------------------------------------------------------------
// Kernel 0a: split weights fp32 -> fp16 hi/lo
// ---------------------------------------------------------------------------
__global__ __launch_bounds__(256) void wsplit_kernel(
    const float* __restrict__ wq, const float* __restrict__ wk,
    const float* __restrict__ wv)
{
    const int idx = blockIdx.x * 256 + threadIdx.x;
    const int which = idx / (CC * CC);
    const int off = idx % (CC * CC);
    const float* src = (which == 0) ? wq : (which == 1) ? wk : wv;
    float v = src[off];
    __half h = __float2half(v);
    g_wh[idx] = h;
    g_wl[idx] = __float2half(v - __half2float(h));
}

// ---------------------------------------------------------------------------
// Kernel 0b: transpose+split X[B,C,N] -> Xt hi/lo [B,N,C]
// ---------------------------------------------------------------------------
__global__ __launch_bounds__(256) void transpose_kernel(const float* __restrict__ x)
{
    __shared__ float t[32][33];
    const int b = blockIdx.z;
    const int n0 = blockIdx.x * 32;
    const int c0 = blockIdx.y * 32;
    const int tx = threadIdx.x & 31;
    const int ty = threadIdx.x >> 5;
    const float* X = x + (size_t)b * CC * NN;
    __half* Xh = g_xth + (size_t)b * NN * CC;
    __half* Xl = g_xtl + (size_t)b * NN * CC;
#pragma unroll
    for (int r = 0; r < 4; ++r)
        t[ty + r * 8][tx] = X[(size_t)(c0 + ty + r * 8) * NN + n0 + tx];
    __syncthreads();
#pragma unroll
    for (int r = 0; r < 4; ++r) {
        float v = t[tx][ty + r * 8];
        __half h = __float2half(v);
        const size_t o = (size_t)(n0 + ty + r * 8) * CC + c0 + tx;
        Xh[o] = h;
        Xl[o] = __float2half(v - __half2float(h));
    }
}

// ---------------------------------------------------------------------------
// Kernel 1: QKV.  proj 0 (3-term): Qt hi [n,d].  proj 1 (3-term): Kt hi/lo.
//                 proj 2 (1-term): V hi [d,n].
// ---------------------------------------------------------------------------
__global__ __launch_bounds__(256, 2) void qkv_kernel(
    const float* __restrict__ bq, const float* __restrict__ bk,
    const float* __restrict__ bv)
{
    __shared__ __align__(16) char smem[SMEM_TOT3];
    const int z = blockIdx.z;
    const int b = z / 3, proj = z % 3;
    const float* bias = (proj == 0) ? bq : (proj == 1) ? bk : bv;
    const __half* Wh = g_wh + (size_t)proj * CC * CC;
    const __half* Wl = g_wl + (size_t)proj * CC * CC;
    const __half* Xh = g_xth + (size_t)b * NN * CC;
    const __half* Xl = g_xtl + (size_t)b * NN * CC;

    float acc[4][4][4] = {};

    if (proj < 2) {
        const int n0 = blockIdx.x * 128;
        const int d0 = blockIdx.y * 128;
        gemm3(Xh + (size_t)n0 * CC, Xl + (size_t)n0 * CC, CC,
              Wh + (size_t)d0 * CC, Wl + (size_t)d0 * CC, CC,
              CC / 16, smem, acc);
        EPILOG_VARS();
        __half* dh = ((proj == 0) ? g_qth : g_kth) + (size_t)b * NN * CC;
        __half* dl = g_ktl + (size_t)b * NN * CC;   // used only when proj==1
#pragma unroll
        for (int mt = 0; mt < 4; ++mt) {
            const int n = n0 + wm * 64 + mt * 16 + g;
#pragma unroll
            for (int nt = 0; nt < 4; ++nt) {
                const int d = d0 + wn * 32 + nt * 8 + tq * 2;
                const float2 bb = *(const float2*)(bias + d);
                __half2 h, l;
                split2(acc[mt][nt][0] + bb.x, acc[mt][nt][1] + bb.y, h, l);
                *(__half2*)(dh + (size_t)n * CC + d) = h;
                if (proj == 1) *(__half2*)(dl + (size_t)n * CC + d) = l;
                split2(acc[mt][nt][2] + bb.x, acc[mt][nt][3] + bb.y, h, l);
                *(__half2*)(dh + (size_t)(n + 8) * CC + d) = h;
                if (proj == 1) *(__half2*)(dl + (size_t)(n + 8) * CC + d) = l;
            }
        }
    } else {
        const int n0 = blockIdx.x * 128;
        const int d0 = blockIdx.y * 128;
        gemm1(Wh + (size_t)d0 * CC, CC, Xh + (size_t)n0 * CC, CC,
              CC / 16, smem, acc);
        EPILOG_VARS();
        __half* dh = g_vh + (size_t)b * CC * NN;
#pragma unroll
        for (int mt = 0; mt < 4; ++mt) {
            const int d = d0 + wm * 64 + mt * 16 + g;
            const float b0 = bias[d], b1 = bias[d + 8];
#pragma unroll
            for (int nt = 0; nt < 4; ++nt) {
                const int n = n0 + wn * 32 + nt * 8 + tq * 2;
                *(__half2*)(dh + (size_t)d * NN + n) =
                    __floats2half2_rn(acc[mt][nt][0] + b0, acc[mt][nt][1] + b0);
                *(__half2*)(dh + (size_t)(d + 8) * NN + n) =
                    __floats2half2_rn(acc[mt][nt][2] + b1, acc[mt][nt][3] + b1);
            }
        }
    }
}

// ---------------------------------------------------------------------------
// Kernel 2: energy (2-term fp16). D[i,j] = Qh·(Kh+Kl)^T -> E fp32 [i,j]
// ---------------------------------------------------------------------------
__global__ __launch_bounds__(256, 2) void energy_kernel()
{
    __shared__ __align__(16) char smem[SMEM_TOT2];
    const int b = blockIdx.z;
    const int i0 = blockIdx.y * 128;
    const int j0 = blockIdx.x * 128;

    float acc[4][4][4] = {};
    gemm2(g_qth + ((size_t)b * NN + i0) * CC, CC,
          g_kth + ((size_t)b * NN + j0) * CC, g_ktl + ((size_t)b * NN + j0) * CC, CC,
          CC / 16, smem, acc);

    EPILOG_VARS();
    float* E = g_e + (size_t)b * NN * NN;
#pragma unroll
    for (int mt = 0; mt < 4; ++mt) {
        const int i = i0 + wm * 64 + mt * 16 + g;
#pragma unroll
        for (int nt = 0; nt < 4; ++nt) {
            const int j = j0 + wn * 32 + nt * 8 + tq * 2;
            __stcs((float2*)(E + (size_t)i * NN + j),
                   make_float2(acc[mt][nt][0], acc[mt][nt][1]));
            __stcs((float2*)(E + (size_t)(i + 8) * NN + j),
                   make_float2(acc[mt][nt][2], acc[mt][nt][3]));
        }
    }
}

// ---------------------------------------------------------------------------
// Kernel 3: row softmax, E fp32 -> P hi fp16. Streaming on both sides.
// ---------------------------------------------------------------------------
__global__ __launch_bounds__(256) void softmax_kernel()
{
    const size_t row = blockIdx.x;
    const float* p = g_e + row * (size_t)NN;
    uint2* ph2 = (uint2*)(g_ph + row * (size_t)NN);   // 2 x half2 per uint2
    const int tid = threadIdx.x;

    float4 v[4];
    float mx = -1e30f;
#pragma unroll
    for (int t = 0; t < 4; ++t) {
        v[t] = __ldcs(&((const float4*)p)[tid + t * 256]);
        mx = fmaxf(mx, fmaxf(fmaxf(v[t].x, v[t].y), fmaxf(v[t].z, v[t].w)));
    }
    __shared__ float red[8];
#pragma unroll
    for (int o = 16; o > 0; o >>= 1) mx = fmaxf(mx, __shfl_xor_sync(0xffffffffu, mx, o));
    if ((tid & 31) == 0) red[tid >> 5] = mx;
    __syncthreads();
    mx = red[0];
#pragma unroll
    for (int w = 1; w < 8; ++w) mx = fmaxf(mx, red[w]);
    __syncthreads();

    float sum = 0.f;
#pragma unroll
    for (int t = 0; t < 4; ++t) {
        v[t].x = __expf(v[t].x - mx); v[t].y = __expf(v[t].y - mx);
        v[t].z = __expf(v[t].z - mx); v[t].w = __expf(v[t].w - mx);
        sum += v[t].x + v[t].y + v[t].z + v[t].w;
    }
#pragma unroll
    for (int o = 16; o > 0; o >>= 1) sum += __shfl_xor_sync(0xffffffffu, sum, o);
    if ((tid & 31) == 0) red[tid >> 5] = sum;
    __syncthreads();
    sum = 0.f;
#pragma unroll
    for (int w = 0; w < 8; ++w) sum += red[w];

    const float inv = 1.0f / sum;
#pragma unroll
    for (int t = 0; t < 4; ++t) {
        __half2 h0 = __floats2half2_rn(v[t].x * inv, v[t].y * inv);
        __half2 h1 = __floats2half2_rn(v[t].z * inv, v[t].w * inv);
        uint2 pk;
        pk.x = *(uint32_t*)&h0;
        pk.y = *(uint32_t*)&h1;
        __stcs(&ph2[tid + t * 256], pk);
    }
}

// ---------------------------------------------------------------------------
// Kernel 4: VA + residual (1-term fp16). D[c,i] = Vh·Ph^T -> out[c,i]
// ---------------------------------------------------------------------------
__global__ __launch_bounds__(256, 2) void va_kernel(
    const float* __restrict__ pose, const float* __restrict__ gamma,
    float* __restrict__ out)
{
    __shared__ __align__(16) char smem[SMEM_TOT3];
    const int b = blockIdx.z;
    const int c0 = blockIdx.y * 128;
    const int i0 = blockIdx.x * 128;

    float acc[4][4][4] = {};
    gemm1(g_vh + ((size_t)b * CC + c0) * NN, NN,
          g_ph + ((size_t)b * NN + i0) * NN, NN,
          NN / 16, smem, acc);

    EPILOG_VARS();
    const float gm = gamma[0];
#pragma unroll
    for (int mt = 0; mt < 4; ++mt) {
        const int c = c0 + wm * 64 + mt * 16 + g;
#pragma unroll
        for (int nt = 0; nt < 4; ++nt) {
            const int i = i0 + wn * 32 + nt * 8 + tq * 2;
            const size_t i1 = ((size_t)b * CC + c) * NN + i;
            const size_t i2 = ((size_t)b * CC + c + 8) * NN + i;
            float2 p1 = *(const float2*)(pose + i1);
            float2 p2 = *(const float2*)(pose + i2);
            *(float2*)(out + i1) = make_float2(fmaf(gm, acc[mt][nt][0], p1.x),
                                               fmaf(gm, acc[mt][nt][1], p1.y));
            *(float2*)(out + i2) = make_float2(fmaf(gm, acc[mt][nt][2], p2.x),
                                               fmaf(gm, acc[mt][nt][3], p2.y));
        }
    }
}

// ---------------------------------------------------------------------------
extern "C" void kernel_launch(void* const* d_in, const int* in_sizes, int n_in,
                              void* d_out, int out_size)
{
    const float* pose  = (const float*)d_in[0];
    const float* wq    = (const float*)d_in[1];
    const float* bq    = (const float*)d_in[2];
    const float* wk    = (const float*)d_in[3];
    const float* bk    = (const float*)d_in[4];
    const float* wv    = (const float*)d_in[5];
    const float* bv    = (const float*)d_in[6];
    const float* gamma = (const float*)d_in[7];
    float* out = (float*)d_out;

    wsplit_kernel   <<<3 * CC * CC / 256, 256>>>(wq, wk, wv);
    transpose_kernel<<<dim3(NN / 32, CC / 32, BB), 256>>>(pose);
    qkv_kernel      <<<dim3(NN / 128, CC / 128, 3 * BB), 256>>>(bq, bk, bv);
    energy_kernel   <<<dim3(NN / 128, NN / 128, BB), 256>>>();
    softmax_kernel  <<<dim3(BB * NN), 256>>>();
    va_kernel       <<<dim3(NN / 128, CC / 128, BB), 256>>>(pose, gamma, out);
}